// round 2
// baseline (speedup 1.0000x reference)
#include <cuda_runtime.h>
#include <cstdint>

#define EMBED 1024
#define HEAD  128
#define SEQ   4096
#define BATCH 4

// Scratch (device globals: no allocations allowed)
static __device__ float g_q [(size_t)BATCH * SEQ * HEAD];   // [b][s][h]
static __device__ float g_kT[(size_t)BATCH * HEAD * SEQ];   // K transposed per batch: [b][h][s]
static __device__ float g_v [(size_t)BATCH * SEQ * HEAD];   // [b][s][h]

typedef unsigned long long u64;

__device__ __forceinline__ u64 pack2(float lo, float hi) {
    u64 r; asm("mov.b64 %0, {%1, %2};" : "=l"(r) : "f"(lo), "f"(hi)); return r;
}
__device__ __forceinline__ void unpack2(u64 v, float& lo, float& hi) {
    asm("mov.b64 {%0, %1}, %2;" : "=f"(lo), "=f"(hi) : "l"(v));
}
__device__ __forceinline__ u64 fma2(u64 a, u64 b, u64 c) {
    u64 d; asm("fma.rn.f32x2 %0, %1, %2, %3;" : "=l"(d) : "l"(a), "l"(b), "l"(c)); return d;
}
__device__ __forceinline__ u64 mul2(u64 a, u64 b) {
    u64 d; asm("mul.rn.f32x2 %0, %1, %2;" : "=l"(d) : "l"(a), "l"(b)); return d;
}

// ============================================================================
// Kernel 1: fused QKV projection.
// Block: 128 threads (tid = output head column h). 16 rows of x per block.
// x chunk staged in smem TRANSPOSED ([e][row], row-pairs contiguous) so a
// single LDS.64 feeds a packed f32x2 FMA for two rows at once.
// K is written transposed (g_kT[b][h][s]) for the attention kernel.
// ============================================================================
#define QKV_ROWS 16
#define QKV_EC   128
#define XS_PAD   18   // row-dim padded 16->18 to break STS bank conflicts

__global__ __launch_bounds__(128) void qkv_kernel(
    const float* __restrict__ x,
    const float* __restrict__ Wq,
    const float* __restrict__ Wk,
    const float* __restrict__ Wv)
{
    __shared__ __align__(16) float xs[QKV_EC * XS_PAD];  // xs[e][r]
    const int tid = threadIdx.x;
    const int R0  = blockIdx.x * QKV_ROWS;

    u64 aq[8], ak[8], av[8];
#pragma unroll
    for (int p = 0; p < 8; p++) { aq[p] = 0ull; ak[p] = 0ull; av[p] = 0ull; }

    for (int ec = 0; ec < EMBED; ec += QKV_EC) {
        __syncthreads();
        // thread tid owns e = tid for this chunk; write transposed
#pragma unroll
        for (int r = 0; r < QKV_ROWS; r++)
            xs[tid * XS_PAD + r] = x[(size_t)(R0 + r) * EMBED + ec + tid];
        __syncthreads();

#pragma unroll 4
        for (int e = 0; e < QKV_EC; e++) {
            const float wq = Wq[(size_t)(ec + e) * HEAD + tid];
            const float wk = Wk[(size_t)(ec + e) * HEAD + tid];
            const float wv = Wv[(size_t)(ec + e) * HEAD + tid];
            const u64 wq2 = pack2(wq, wq);
            const u64 wk2 = pack2(wk, wk);
            const u64 wv2 = pack2(wv, wv);
#pragma unroll
            for (int p = 0; p < 8; p++) {
                const u64 xv2 = *reinterpret_cast<const u64*>(&xs[e * XS_PAD + 2 * p]);
                aq[p] = fma2(xv2, wq2, aq[p]);
                ak[p] = fma2(xv2, wk2, ak[p]);
                av[p] = fma2(xv2, wv2, av[p]);
            }
        }
    }

    const int b  = R0 >> 12;        // R0 / 4096
    const int rb = R0 & (SEQ - 1);  // row within batch
#pragma unroll
    for (int p = 0; p < 8; p++) {
        float q0, q1, k0, k1, v0, v1;
        unpack2(aq[p], q0, q1);
        unpack2(ak[p], k0, k1);
        unpack2(av[p], v0, v1);
        const size_t r0g = (size_t)(R0 + 2 * p) * HEAD + tid;
        g_q[r0g]        = q0;
        g_q[r0g + HEAD] = q1;
        g_v[r0g]        = v0;
        g_v[r0g + HEAD] = v1;
        const size_t kt0 = ((size_t)b * HEAD + tid) * SEQ + rb + 2 * p;
        g_kT[kt0]     = k0;
        g_kT[kt0 + 1] = k1;
    }
}

// ============================================================================
// Kernel 2: causal flash attention, fp32 with f32x2 packed FMAs.
// Block = 256 threads (ty = tid/16 rows, tx = tid%16 cols).
// BQ = BK = 64. Scores: thread tile 4 rows x 4 cols (2 col-pairs packed).
// AV:     thread tile 4 rows x 8 h  (h = 2*tx + 32*c, conflict-free LDS.64).
// Smem: Qs[64][128] + Ks[128][64] (e-major) + Vs[64][128] + Ps[64][64].
// ============================================================================
#define BQ 64
#define BK 64
#define NEG_BIG (-3.0e38f)

__global__ __launch_bounds__(256, 1) void attn_kernel(float* __restrict__ out)
{
    extern __shared__ __align__(16) float sm[];
    float* Qs = sm;                    // [64][128]
    float* Ks = Qs + BQ * HEAD;        // [128][64]  Ks[e][k]
    float* Vs = Ks + HEAD * BK;        // [64][128]
    float* Ps = Vs + BK * HEAD;        // [64][64]

    const int tid = threadIdx.x;
    const int tx  = tid & 15;
    const int ty  = tid >> 4;
    const int b   = blockIdx.y;
    const int qt  = gridDim.x - 1 - blockIdx.x;   // largest-first for makespan
    const int q0  = qt * BQ;
    const float scale = 0.08838834764831845f;     // 1/sqrt(128)

    // Load Q tile, pre-scaled
    {
        const float* qg = g_q + ((size_t)b * SEQ + q0) * HEAD;
        for (int idx = tid; idx < BQ * (HEAD / 4); idx += 256) {
            const int r = idx >> 5, c4 = idx & 31;
            float4 v = *reinterpret_cast<const float4*>(qg + (size_t)r * HEAD + c4 * 4);
            v.x *= scale; v.y *= scale; v.z *= scale; v.w *= scale;
            *reinterpret_cast<float4*>(Qs + r * HEAD + c4 * 4) = v;
        }
    }

    u64 O2[4][4];            // [row i][col-pair c], h = 2*tx + 32*c (+0/+1)
#pragma unroll
    for (int i = 0; i < 4; i++)
#pragma unroll
        for (int c = 0; c < 4; c++) O2[i][c] = 0ull;
    float m[4], l[4];
#pragma unroll
    for (int i = 0; i < 4; i++) { m[i] = NEG_BIG; l[i] = 0.0f; }

    const int nk = qt + 1;
    for (int kt = 0; kt < nk; kt++) {
        __syncthreads();   // protect Ks/Vs/Ps from previous iteration readers

        // Load K tile (already transposed in gmem -> conflict-free stores)
        {
            const float* kg = g_kT + (size_t)b * HEAD * SEQ + kt * BK;
            for (int idx = tid; idx < HEAD * (BK / 4); idx += 256) {
                const int e = idx >> 4, k4 = idx & 15;
                *reinterpret_cast<float4*>(Ks + e * BK + k4 * 4) =
                    *reinterpret_cast<const float4*>(kg + (size_t)e * SEQ + k4 * 4);
            }
        }
        // Load V tile (natural layout)
        {
            const float* vg = g_v + ((size_t)b * SEQ + kt * BK) * HEAD;
            for (int idx = tid; idx < BK * (HEAD / 4); idx += 256) {
                const int r = idx >> 5, c4 = idx & 31;
                *reinterpret_cast<float4*>(Vs + r * HEAD + c4 * 4) =
                    *reinterpret_cast<const float4*>(vg + (size_t)r * HEAD + c4 * 4);
            }
        }
        __syncthreads();

        // ---- scores: S = Q K^T (4x4 per thread, cols packed in pairs) ----
        u64 s2[4][2];
#pragma unroll
        for (int i = 0; i < 4; i++) { s2[i][0] = 0ull; s2[i][1] = 0ull; }

#pragma unroll 4
        for (int e = 0; e < HEAD; e++) {
            const u64 k2a = *reinterpret_cast<const u64*>(Ks + e * BK + tx * 4);
            const u64 k2b = *reinterpret_cast<const u64*>(Ks + e * BK + tx * 4 + 2);
#pragma unroll
            for (int i = 0; i < 4; i++) {
                const float qv = Qs[(ty * 4 + i) * HEAD + e];
                const u64 q2 = pack2(qv, qv);
                s2[i][0] = fma2(q2, k2a, s2[i][0]);
                s2[i][1] = fma2(q2, k2b, s2[i][1]);
            }
        }

        float s[4][4];
#pragma unroll
        for (int i = 0; i < 4; i++) {
            unpack2(s2[i][0], s[i][0], s[i][1]);
            unpack2(s2[i][1], s[i][2], s[i][3]);
        }

        // causal mask on diagonal tile
        if (kt == qt) {
#pragma unroll
            for (int i = 0; i < 4; i++)
#pragma unroll
                for (int j = 0; j < 4; j++)
                    if (tx * 4 + j > ty * 4 + i) s[i][j] = NEG_BIG;
        }

        // ---- online softmax ----
#pragma unroll
        for (int i = 0; i < 4; i++) {
            float rm = fmaxf(fmaxf(s[i][0], s[i][1]), fmaxf(s[i][2], s[i][3]));
#pragma unroll
            for (int off = 1; off < 16; off <<= 1)
                rm = fmaxf(rm, __shfl_xor_sync(0xffffffffu, rm, off));
            const float nm = fmaxf(m[i], rm);
            const float a  = __expf(m[i] - nm);
            const float p0 = __expf(s[i][0] - nm);
            const float p1 = __expf(s[i][1] - nm);
            const float p2 = __expf(s[i][2] - nm);
            const float p3 = __expf(s[i][3] - nm);
            float sum = (p0 + p1) + (p2 + p3);
#pragma unroll
            for (int off = 1; off < 16; off <<= 1)
                sum += __shfl_xor_sync(0xffffffffu, sum, off);
            l[i] = l[i] * a + sum;
            m[i] = nm;
            // store probabilities
            float4 pv; pv.x = p0; pv.y = p1; pv.z = p2; pv.w = p3;
            *reinterpret_cast<float4*>(Ps + (ty * 4 + i) * BK + tx * 4) = pv;
            // rescale O
            const u64 a2 = pack2(a, a);
#pragma unroll
            for (int c = 0; c < 4; c++) O2[i][c] = mul2(O2[i][c], a2);
        }
        __syncthreads();

        // ---- AV: O += P V ----
#pragma unroll 2
        for (int k = 0; k < BK; k++) {
            u64 v2[4];
#pragma unroll
            for (int c = 0; c < 4; c++)
                v2[c] = *reinterpret_cast<const u64*>(Vs + k * HEAD + 2 * tx + 32 * c);
#pragma unroll
            for (int i = 0; i < 4; i++) {
                const float pv = Ps[(ty * 4 + i) * BK + k];
                const u64 p2 = pack2(pv, pv);
#pragma unroll
                for (int c = 0; c < 4; c++)
                    O2[i][c] = fma2(p2, v2[c], O2[i][c]);
            }
        }
    }

    // ---- epilogue: divide by l, write out ----
    float* og = out + ((size_t)b * SEQ + q0) * HEAD;
#pragma unroll
    for (int i = 0; i < 4; i++) {
        const float inv = 1.0f / l[i];
#pragma unroll
        for (int c = 0; c < 4; c++) {
            float o0, o1;
            unpack2(O2[i][c], o0, o1);
            const size_t base = (size_t)(ty * 4 + i) * HEAD + 2 * tx + 32 * c;
            og[base]     = o0 * inv;
            og[base + 1] = o1 * inv;
        }
    }
}

// ============================================================================
// Launch
// ============================================================================
extern "C" void kernel_launch(void* const* d_in, const int* in_sizes, int n_in,
                              void* d_out, int out_size)
{
    const float* x  = (const float*)d_in[0];
    const float* Wq = (const float*)d_in[1];
    const float* Wk = (const float*)d_in[2];
    const float* Wv = (const float*)d_in[3];
    float* out = (float*)d_out;

    qkv_kernel<<<(BATCH * SEQ) / QKV_ROWS, 128>>>(x, Wq, Wk, Wv);

    const int smem_bytes = (BQ * HEAD + HEAD * BK + BK * HEAD + BQ * BK) * (int)sizeof(float);
    (void)cudaFuncSetAttribute(attn_kernel, cudaFuncAttributeMaxDynamicSharedMemorySize, smem_bytes);
    dim3 grid(SEQ / BQ, BATCH);
    attn_kernel<<<grid, 256, smem_bytes>>>(out);
}

// round 4
// speedup vs baseline: 1.3710x; 1.3710x over previous
#include <cuda_runtime.h>
#include <cstdint>

#define EMBED 1024
#define HEAD  128
#define SEQ   4096
#define BATCH 4
#define ROWS_TOTAL (BATCH*SEQ)

typedef unsigned long long u64;

// scratch (device globals; no allocations allowed)
static __device__ float g_q [(size_t)ROWS_TOTAL * HEAD];
static __device__ float g_kT[(size_t)BATCH * HEAD * SEQ];    // [b][h][s]
static __device__ float g_v [(size_t)ROWS_TOTAL * HEAD];
static __device__ float g_part[(size_t)2 * ROWS_TOTAL * HEAD]; // unnormalized O per split
static __device__ float g_mp[2 * ROWS_TOTAL];
static __device__ float g_lp[2 * ROWS_TOTAL];

__device__ __forceinline__ u64 pack2(float lo, float hi) {
    u64 r; asm("mov.b64 %0, {%1, %2};" : "=l"(r) : "f"(lo), "f"(hi)); return r;
}
__device__ __forceinline__ void unpack2(u64 v, float& lo, float& hi) {
    asm("mov.b64 {%0, %1}, %2;" : "=f"(lo), "=f"(hi) : "l"(v));
}
__device__ __forceinline__ u64 fma2(u64 a, u64 b, u64 c) {
    u64 d; asm("fma.rn.f32x2 %0, %1, %2, %3;" : "=l"(d) : "l"(a), "l"(b), "l"(c)); return d;
}
__device__ __forceinline__ u64 mul2(u64 a, u64 b) {
    u64 d; asm("mul.rn.f32x2 %0, %1, %2;" : "=l"(d) : "l"(a), "l"(b)); return d;
}

// ============================================================================
// Kernel 1: fused QKV projection (unchanged, proven: ~386us)
// ============================================================================
#define QKV_ROWS 16
#define QKV_EC   128
#define XS_PAD   18

__global__ __launch_bounds__(128) void qkv_kernel(
    const float* __restrict__ x, const float* __restrict__ Wq,
    const float* __restrict__ Wk, const float* __restrict__ Wv)
{
    __shared__ __align__(16) float xs[QKV_EC * XS_PAD];
    const int tid = threadIdx.x;
    const int R0  = blockIdx.x * QKV_ROWS;

    u64 aq[8], ak[8], av[8];
#pragma unroll
    for (int p = 0; p < 8; p++) { aq[p] = 0ull; ak[p] = 0ull; av[p] = 0ull; }

    for (int ec = 0; ec < EMBED; ec += QKV_EC) {
        __syncthreads();
#pragma unroll
        for (int r = 0; r < QKV_ROWS; r++)
            xs[tid * XS_PAD + r] = x[(size_t)(R0 + r) * EMBED + ec + tid];
        __syncthreads();
#pragma unroll 4
        for (int e = 0; e < QKV_EC; e++) {
            const float wq = Wq[(size_t)(ec + e) * HEAD + tid];
            const float wk = Wk[(size_t)(ec + e) * HEAD + tid];
            const float wv = Wv[(size_t)(ec + e) * HEAD + tid];
            const u64 wq2 = pack2(wq, wq), wk2 = pack2(wk, wk), wv2 = pack2(wv, wv);
#pragma unroll
            for (int p = 0; p < 8; p++) {
                const u64 xv2 = *reinterpret_cast<const u64*>(&xs[e * XS_PAD + 2 * p]);
                aq[p] = fma2(xv2, wq2, aq[p]);
                ak[p] = fma2(xv2, wk2, ak[p]);
                av[p] = fma2(xv2, wv2, av[p]);
            }
        }
    }
    const int b = R0 >> 12, rb = R0 & (SEQ - 1);
#pragma unroll
    for (int p = 0; p < 8; p++) {
        float q0, q1, k0, k1, v0, v1;
        unpack2(aq[p], q0, q1); unpack2(ak[p], k0, k1); unpack2(av[p], v0, v1);
        const size_t r0g = (size_t)(R0 + 2 * p) * HEAD + tid;
        g_q[r0g] = q0; g_q[r0g + HEAD] = q1;
        g_v[r0g] = v0; g_v[r0g + HEAD] = v1;
        const size_t kt0 = ((size_t)b * HEAD + tid) * SEQ + rb + 2 * p;
        g_kT[kt0] = k0; g_kT[kt0 + 1] = k1;
    }
}

// ============================================================================
// Kernel 2: causal flash attention. BQ=128 x BK=64, split-K=2, 256 threads.
// tx=tid%16, ty=tid/16. Scores: 8 rows x 4 cols/thread (rows f32x2-packed).
// AV: 8 rows x 8 h/thread. Smem 160KB: Qs[e][q] Ks[e][k] Vs[k][h] Ps[q][k].
// ============================================================================
#define NEG_BIG (-3.0e38f)
#define M_INIT  (-1.0e30f)
#define ATT_SMEM ((128*128 + 128*64 + 64*128 + 128*64) * 4)

__global__ __launch_bounds__(256, 1) void attn_kernel()
{
    extern __shared__ __align__(16) float smf[];
    float* Qs = smf;             // [e][q] 128x128
    float* Ks = Qs + 128 * 128;  // [e][k] 128x64
    float* Vs = Ks + 128 * 64;   // [k][h] 64x128
    float* Ps = Vs + 64 * 128;   // [q][k] 128x64

    const int tid = threadIdx.x;
    const int tx = tid & 15, ty = tid >> 4;
    const int id = blockIdx.x;                 // 256 = 32 qt * 2 z * 4 b
    const int qt = 31 - (id >> 3);             // largest first
    const int z  = id & 1;
    const int b  = (id >> 1) & 3;
    const int q0 = qt * 128;
    const float scale = 0.08838834764831845f;  // 1/sqrt(128)

    // Q -> smem transposed [e][q], pre-scaled
    {
        const float* qg = g_q + ((size_t)b * SEQ + q0) * HEAD;
#pragma unroll
        for (int i = 0; i < 16; i++) {
            int idx = tid + i * 256;
            int h4 = idx >> 7, r = idx & 127;
            float4 v = *(const float4*)(qg + (size_t)r * HEAD + h4 * 4);
            Qs[(h4 * 4 + 0) * 128 + r] = v.x * scale;
            Qs[(h4 * 4 + 1) * 128 + r] = v.y * scale;
            Qs[(h4 * 4 + 2) * 128 + r] = v.z * scale;
            Qs[(h4 * 4 + 3) * 128 + r] = v.w * scale;
        }
    }

    u64 O2[8][4];
    float m[8], l[8];
#pragma unroll
    for (int i = 0; i < 8; i++) {
        m[i] = M_INIT; l[i] = 0.0f;
#pragma unroll
        for (int hp = 0; hp < 4; hp++) O2[i][hp] = 0ull;
    }

    const int kt0 = z ? (qt + 1) : 0;
    const int kt1 = z ? (2 * qt + 2) : (qt + 1);

    for (int kt = kt0; kt < kt1; kt++) {
        __syncthreads();
        {   // K tile [e][k]
            const float* kg = g_kT + (size_t)b * HEAD * SEQ + (size_t)kt * 64;
#pragma unroll
            for (int i = 0; i < 8; i++) {
                int idx = tid + i * 256;
                int e = idx >> 4, k4 = idx & 15;
                *(float4*)(Ks + e * 64 + k4 * 4) =
                    *(const float4*)(kg + (size_t)e * SEQ + k4 * 4);
            }
        }
        {   // V tile [k][h]
            const float* vg = g_v + ((size_t)b * SEQ + (size_t)kt * 64) * HEAD;
#pragma unroll
            for (int i = 0; i < 8; i++) {
                int idx = tid + i * 256;
                int r = idx >> 5, h4 = idx & 31;
                *(float4*)(Vs + r * 128 + h4 * 4) =
                    *(const float4*)(vg + (size_t)r * HEAD + h4 * 4);
            }
        }
        __syncthreads();

        // ---- scores ----
        u64 s2[4][4];
#pragma unroll
        for (int rp = 0; rp < 4; rp++)
#pragma unroll
            for (int j = 0; j < 4; j++) s2[rp][j] = 0ull;

#pragma unroll 2
        for (int e = 0; e < 128; e++) {
            float4 kv = *(const float4*)(Ks + e * 64 + tx * 4);
            u64 k2[4] = { pack2(kv.x, kv.x), pack2(kv.y, kv.y),
                          pack2(kv.z, kv.z), pack2(kv.w, kv.w) };
            const float* qrow = Qs + e * 128 + ty * 8;
            float4 qa = *(const float4*)(qrow);
            float4 qb = *(const float4*)(qrow + 4);
            u64 q2[4] = { pack2(qa.x, qa.y), pack2(qa.z, qa.w),
                          pack2(qb.x, qb.y), pack2(qb.z, qb.w) };
#pragma unroll
            for (int rp = 0; rp < 4; rp++)
#pragma unroll
                for (int j = 0; j < 4; j++)
                    s2[rp][j] = fma2(q2[rp], k2[j], s2[rp][j]);
        }

        float s[8][4];
#pragma unroll
        for (int rp = 0; rp < 4; rp++)
#pragma unroll
            for (int j = 0; j < 4; j++)
                unpack2(s2[rp][j], s[2 * rp][j], s[2 * rp + 1][j]);

        if (kt >= 2 * qt) {   // diagonal-straddling tiles
            const int koff = (kt - 2 * qt) * 64;
#pragma unroll
            for (int i = 0; i < 8; i++)
#pragma unroll
                for (int j = 0; j < 4; j++)
                    if (koff + tx * 4 + j > ty * 8 + i) s[i][j] = NEG_BIG;
        }

        // ---- online softmax (reduce over 16 tx lanes) ----
#pragma unroll
        for (int i = 0; i < 8; i++) {
            float rm = fmaxf(fmaxf(s[i][0], s[i][1]), fmaxf(s[i][2], s[i][3]));
#pragma unroll
            for (int off = 1; off < 16; off <<= 1)
                rm = fmaxf(rm, __shfl_xor_sync(0xffffffffu, rm, off));
            const float nm = fmaxf(m[i], rm);
            const float a  = __expf(m[i] - nm);
            const float p0 = __expf(s[i][0] - nm);
            const float p1 = __expf(s[i][1] - nm);
            const float p2 = __expf(s[i][2] - nm);
            const float p3 = __expf(s[i][3] - nm);
            float sum = (p0 + p1) + (p2 + p3);
#pragma unroll
            for (int off = 1; off < 16; off <<= 1)
                sum += __shfl_xor_sync(0xffffffffu, sum, off);
            l[i] = l[i] * a + sum;
            m[i] = nm;
            float4 pv; pv.x = p0; pv.y = p1; pv.z = p2; pv.w = p3;
            *(float4*)(Ps + (ty * 8 + i) * 64 + tx * 4) = pv;
            const u64 a2 = pack2(a, a);
#pragma unroll
            for (int hp = 0; hp < 4; hp++) O2[i][hp] = mul2(O2[i][hp], a2);
        }
        __syncthreads();

        // ---- AV: P chunked in float4 to cut LDS issue count ----
#pragma unroll 2
        for (int k4 = 0; k4 < 16; k4++) {
            float4 pr[8];
#pragma unroll
            for (int i = 0; i < 8; i++)
                pr[i] = *(const float4*)(Ps + (ty * 8 + i) * 64 + k4 * 4);
#pragma unroll
            for (int kk = 0; kk < 4; kk++) {
                const int k = k4 * 4 + kk;
                const float* vrow = Vs + k * 128 + tx * 8;
                float4 va = *(const float4*)(vrow);
                float4 vb = *(const float4*)(vrow + 4);
                u64 v2[4] = { pack2(va.x, va.y), pack2(va.z, va.w),
                              pack2(vb.x, vb.y), pack2(vb.z, vb.w) };
#pragma unroll
                for (int i = 0; i < 8; i++) {
                    const float pv = (kk == 0) ? pr[i].x : (kk == 1) ? pr[i].y
                                   : (kk == 2) ? pr[i].z : pr[i].w;
                    const u64 p2 = pack2(pv, pv);
#pragma unroll
                    for (int hp = 0; hp < 4; hp++)
                        O2[i][hp] = fma2(p2, v2[hp], O2[i][hp]);
                }
            }
        }
    }

    // ---- write unnormalized partials ----
    const size_t base = (size_t)(z * BATCH + b) * SEQ + q0;
#pragma unroll
    for (int i = 0; i < 8; i++) {
        const int r = ty * 8 + i;
        float* op = g_part + (base + r) * HEAD + tx * 8;
        *(u64*)(op + 0) = O2[i][0];
        *(u64*)(op + 2) = O2[i][1];
        *(u64*)(op + 4) = O2[i][2];
        *(u64*)(op + 6) = O2[i][3];
        if (tx == 0) { g_mp[base + r] = m[i]; g_lp[base + r] = l[i]; }
    }
}

// ============================================================================
// Kernel 3: merge the 2 split-K partials
// ============================================================================
__global__ __launch_bounds__(256) void combine_kernel(float* __restrict__ out)
{
    const int idx = blockIdx.x * 256 + threadIdx.x;   // ROWS_TOTAL*32 threads
    const int row = idx >> 5, h4 = idx & 31;
    const float m0 = g_mp[row], m1 = g_mp[ROWS_TOTAL + row];
    const float l0 = g_lp[row], l1 = g_lp[ROWS_TOTAL + row];
    const float mm = fmaxf(m0, m1);
    const float a0 = __expf(m0 - mm), a1 = __expf(m1 - mm);
    const float inv = 1.0f / (l0 * a0 + l1 * a1);
    const float4 o0 = *(const float4*)(g_part + (size_t)row * HEAD + h4 * 4);
    const float4 o1 = *(const float4*)(g_part + ((size_t)ROWS_TOTAL + row) * HEAD + h4 * 4);
    float4 r;
    r.x = (o0.x * a0 + o1.x * a1) * inv;
    r.y = (o0.y * a0 + o1.y * a1) * inv;
    r.z = (o0.z * a0 + o1.z * a1) * inv;
    r.w = (o0.w * a0 + o1.w * a1) * inv;
    *(float4*)(out + (size_t)row * HEAD + h4 * 4) = r;
}

// ============================================================================
extern "C" void kernel_launch(void* const* d_in, const int* in_sizes, int n_in,
                              void* d_out, int out_size)
{
    const float* x  = (const float*)d_in[0];
    const float* Wq = (const float*)d_in[1];
    const float* Wk = (const float*)d_in[2];
    const float* Wv = (const float*)d_in[3];
    float* out = (float*)d_out;

    qkv_kernel<<<(BATCH * SEQ) / QKV_ROWS, 128>>>(x, Wq, Wk, Wv);

    (void)cudaFuncSetAttribute(attn_kernel,
        cudaFuncAttributeMaxDynamicSharedMemorySize, ATT_SMEM);
    attn_kernel<<<256, 256, ATT_SMEM>>>();

    combine_kernel<<<(ROWS_TOTAL * 32) / 256, 256>>>(out);
}

// round 6
// speedup vs baseline: 1.9566x; 1.4271x over previous
#include <cuda_runtime.h>
#include <cstdint>

#define EMBED 1024
#define HEAD  128
#define SEQ   4096
#define BATCH 4
#define ROWS_TOTAL (BATCH*SEQ)

typedef unsigned long long u64;
typedef unsigned int u32;

// scratch (device globals; no allocations allowed)
static __device__ float g_q [(size_t)ROWS_TOTAL * HEAD];
static __device__ float g_kT[(size_t)BATCH * HEAD * SEQ];      // [b][h][s]
static __device__ float g_v [(size_t)ROWS_TOTAL * HEAD];
static __device__ float g_part[(size_t)2 * ROWS_TOTAL * HEAD];
static __device__ float g_mp[2 * ROWS_TOTAL];
static __device__ float g_lp[2 * ROWS_TOTAL];

__device__ __forceinline__ u64 pack2(float lo, float hi) {
    u64 r; asm("mov.b64 %0, {%1, %2};" : "=l"(r) : "f"(lo), "f"(hi)); return r;
}
__device__ __forceinline__ void unpack2(u64 v, float& lo, float& hi) {
    asm("mov.b64 {%0, %1}, %2;" : "=f"(lo), "=f"(hi) : "l"(v));
}
__device__ __forceinline__ u64 fma2(u64 a, u64 b, u64 c) {
    u64 d; asm("fma.rn.f32x2 %0, %1, %2, %3;" : "=l"(d) : "l"(a), "l"(b), "l"(c)); return d;
}
__device__ __forceinline__ u64 mul2(u64 a, u64 b) {
    u64 d; asm("mul.rn.f32x2 %0, %1, %2;" : "=l"(d) : "l"(a), "l"(b)); return d;
}
__device__ __forceinline__ u32 tf32_rna(float f) {
    u32 r; asm("cvt.rna.tf32.f32 %0, %1;" : "=r"(r) : "f"(f)); return r;
}
__device__ __forceinline__ void mma_tf32(float* d, u32 a0, u32 a1, u32 a2, u32 a3,
                                         u32 b0, u32 b1) {
    asm volatile("mma.sync.aligned.m16n8k8.row.col.f32.tf32.tf32.f32 "
        "{%0,%1,%2,%3}, {%4,%5,%6,%7}, {%8,%9}, {%0,%1,%2,%3};"
        : "+f"(d[0]), "+f"(d[1]), "+f"(d[2]), "+f"(d[3])
        : "r"(a0), "r"(a1), "r"(a2), "r"(a3), "r"(b0), "r"(b1));
}

// ============================================================================
// Kernel 1: QKV projection via mma.sync tf32 (tensor pipe).
// grid (128 M-tiles, 3 weights), 256 threads = 8 warps (2x4), warp m64 x n32.
// As[m][k] stride 36 (frag-LDS conflict-free); Bs[k][n] stride 136.
// ============================================================================
#define BM 128
#define BN 128
#define BK 32
#define NCH (EMBED / BK)     // 32 chunks
#define AS_STR 36
#define BS_STR 136
#define AS_SZ (BM * AS_STR)  // 4608 floats
#define BS_SZ (BK * BS_STR)  // 4352 floats
#define QKV_SMEM ((AS_SZ + BS_SZ) * 2 * 4)   // 71680 B

__global__ __launch_bounds__(256, 1) void qkv_mma_kernel(
    const float* __restrict__ x, const float* __restrict__ Wq,
    const float* __restrict__ Wk, const float* __restrict__ Wv)
{
    extern __shared__ __align__(16) float smq[];
    const int tid  = threadIdx.x;
    const int lane = tid & 31;
    const int wid  = tid >> 5;
    const int warp_m = (wid >> 2) * 64;
    const int warp_n = (wid & 3) * 32;
    const int m0 = blockIdx.x * BM;
    const int w  = blockIdx.y;
    const float* W = (w == 0) ? Wq : (w == 1) ? Wk : Wv;

    float* Asb[2] = { smq,                     smq + AS_SZ + BS_SZ };
    float* Bsb[2] = { smq + AS_SZ,             smq + 2 * AS_SZ + BS_SZ };

    float4 areg[4], breg[4];

    // ---- ldg chunk c into regs ----
#define LDG_CHUNK(c) do { \
    _Pragma("unroll") \
    for (int i = 0; i < 4; i++) { \
        int idx = tid + i * 256; \
        int row = idx >> 3, kq = idx & 7; \
        areg[i] = *(const float4*)(x + (size_t)(m0 + row) * EMBED + (c) * BK + kq * 4); \
        int k = idx >> 5, nq = idx & 31; \
        breg[i] = *(const float4*)(W + (size_t)((c) * BK + k) * HEAD + nq * 4); \
    } \
} while (0)

    // ---- regs -> smem buf (with tf32 rounding) ----
#define STS_CHUNK(buf) do { \
    _Pragma("unroll") \
    for (int i = 0; i < 4; i++) { \
        int idx = tid + i * 256; \
        int row = idx >> 3, kq = idx & 7; \
        uint4 av = { tf32_rna(areg[i].x), tf32_rna(areg[i].y), \
                     tf32_rna(areg[i].z), tf32_rna(areg[i].w) }; \
        *(uint4*)(Asb[buf] + row * AS_STR + kq * 4) = av; \
        int k = idx >> 5, nq = idx & 31; \
        uint4 bv = { tf32_rna(breg[i].x), tf32_rna(breg[i].y), \
                     tf32_rna(breg[i].z), tf32_rna(breg[i].w) }; \
        *(uint4*)(Bsb[buf] + k * BS_STR + nq * 4) = bv; \
    } \
} while (0)

    float acc[4][4][4];
#pragma unroll
    for (int mf = 0; mf < 4; mf++)
#pragma unroll
        for (int nf = 0; nf < 4; nf++)
#pragma unroll
            for (int i = 0; i < 4; i++) acc[mf][nf][i] = 0.0f;

    LDG_CHUNK(0);
    STS_CHUNK(0);
    __syncthreads();

    for (int c = 0; c < NCH; c++) {
        const int buf = c & 1;
        if (c + 1 < NCH) LDG_CHUNK(c + 1);

        const u32* ap = (const u32*)Asb[buf] + (warp_m + (lane >> 2)) * AS_STR + (lane & 3);
        const u32* bp = (const u32*)Bsb[buf] + (lane & 3) * BS_STR + warp_n + (lane >> 2);
#pragma unroll
        for (int ks = 0; ks < 4; ks++) {
            u32 a[4][4], b[4][2];
#pragma unroll
            for (int mf = 0; mf < 4; mf++) {
                const int o = mf * (16 * AS_STR) + ks * 8;
                a[mf][0] = ap[o];
                a[mf][1] = ap[o + 8 * AS_STR];
                a[mf][2] = ap[o + 4];
                a[mf][3] = ap[o + 8 * AS_STR + 4];
            }
#pragma unroll
            for (int nf = 0; nf < 4; nf++) {
                const int o = ks * (8 * BS_STR) + nf * 8;
                b[nf][0] = bp[o];
                b[nf][1] = bp[o + 4 * BS_STR];
            }
#pragma unroll
            for (int mf = 0; mf < 4; mf++)
#pragma unroll
                for (int nf = 0; nf < 4; nf++)
                    mma_tf32(acc[mf][nf], a[mf][0], a[mf][1], a[mf][2], a[mf][3],
                             b[nf][0], b[nf][1]);
        }

        if (c + 1 < NCH) {
            STS_CHUNK((c + 1) & 1);
            __syncthreads();
        }
    }

    // ---- epilogue ----
    // C frag m16n8: c0 (r=lane/4, n=2*(lane%4)), c1 (r, n+1), c2 (r+8, n), c3 (r+8, n+1)
#pragma unroll
    for (int mf = 0; mf < 4; mf++) {
        const int mrow = m0 + warp_m + mf * 16 + (lane >> 2);
#pragma unroll
        for (int nf = 0; nf < 4; nf++) {
            const int ncol = warp_n + nf * 8 + 2 * (lane & 3);
            if (w == 1) {   // K -> transposed g_kT[b][h][s]
                const int b0 = mrow >> 12, rb = mrow & (SEQ - 1);
                float* kg = g_kT + ((size_t)b0 * HEAD + ncol) * SEQ + rb;
                kg[0]            = acc[mf][nf][0];
                kg[SEQ]          = acc[mf][nf][1];
                kg[8]            = acc[mf][nf][2];
                kg[SEQ + 8]      = acc[mf][nf][3];
            } else {
                float* dst = (w == 0) ? g_q : g_v;
                float* p0 = dst + (size_t)mrow * HEAD + ncol;
                *(u64*)p0              = pack2(acc[mf][nf][0], acc[mf][nf][1]);
                *(u64*)(p0 + 8 * HEAD) = pack2(acc[mf][nf][2], acc[mf][nf][3]);
            }
        }
    }
#undef LDG_CHUNK
#undef STS_CHUNK
}

// ============================================================================
// Kernel 2: causal flash attention (unchanged from passing R4 version)
// ============================================================================
#define NEG_BIG (-3.0e38f)
#define M_INIT  (-1.0e30f)
#define ATT_SMEM ((128*128 + 128*64 + 64*128 + 128*64) * 4)

__global__ __launch_bounds__(256, 1) void attn_kernel()
{
    extern __shared__ __align__(16) float smf[];
    float* Qs = smf;
    float* Ks = Qs + 128 * 128;
    float* Vs = Ks + 128 * 64;
    float* Ps = Vs + 64 * 128;

    const int tid = threadIdx.x;
    const int tx = tid & 15, ty = tid >> 4;
    const int id = blockIdx.x;
    const int qt = 31 - (id >> 3);
    const int z  = id & 1;
    const int b  = (id >> 1) & 3;
    const int q0 = qt * 128;
    const float scale = 0.08838834764831845f;

    {
        const float* qg = g_q + ((size_t)b * SEQ + q0) * HEAD;
#pragma unroll
        for (int i = 0; i < 16; i++) {
            int idx = tid + i * 256;
            int h4 = idx >> 7, r = idx & 127;
            float4 v = *(const float4*)(qg + (size_t)r * HEAD + h4 * 4);
            Qs[(h4 * 4 + 0) * 128 + r] = v.x * scale;
            Qs[(h4 * 4 + 1) * 128 + r] = v.y * scale;
            Qs[(h4 * 4 + 2) * 128 + r] = v.z * scale;
            Qs[(h4 * 4 + 3) * 128 + r] = v.w * scale;
        }
    }

    u64 O2[8][4];
    float m[8], l[8];
#pragma unroll
    for (int i = 0; i < 8; i++) {
        m[i] = M_INIT; l[i] = 0.0f;
#pragma unroll
        for (int hp = 0; hp < 4; hp++) O2[i][hp] = 0ull;
    }

    const int kt0 = z ? (qt + 1) : 0;
    const int kt1 = z ? (2 * qt + 2) : (qt + 1);

    for (int kt = kt0; kt < kt1; kt++) {
        __syncthreads();
        {
            const float* kg = g_kT + (size_t)b * HEAD * SEQ + (size_t)kt * 64;
#pragma unroll
            for (int i = 0; i < 8; i++) {
                int idx = tid + i * 256;
                int e = idx >> 4, k4 = idx & 15;
                *(float4*)(Ks + e * 64 + k4 * 4) =
                    *(const float4*)(kg + (size_t)e * SEQ + k4 * 4);
            }
        }
        {
            const float* vg = g_v + ((size_t)b * SEQ + (size_t)kt * 64) * HEAD;
#pragma unroll
            for (int i = 0; i < 8; i++) {
                int idx = tid + i * 256;
                int r = idx >> 5, h4 = idx & 31;
                *(float4*)(Vs + r * 128 + h4 * 4) =
                    *(const float4*)(vg + (size_t)r * HEAD + h4 * 4);
            }
        }
        __syncthreads();

        u64 s2[4][4];
#pragma unroll
        for (int rp = 0; rp < 4; rp++)
#pragma unroll
            for (int j = 0; j < 4; j++) s2[rp][j] = 0ull;

#pragma unroll 2
        for (int e = 0; e < 128; e++) {
            float4 kv = *(const float4*)(Ks + e * 64 + tx * 4);
            u64 k2[4] = { pack2(kv.x, kv.x), pack2(kv.y, kv.y),
                          pack2(kv.z, kv.z), pack2(kv.w, kv.w) };
            const float* qrow = Qs + e * 128 + ty * 8;
            float4 qa = *(const float4*)(qrow);
            float4 qb = *(const float4*)(qrow + 4);
            u64 q2[4] = { pack2(qa.x, qa.y), pack2(qa.z, qa.w),
                          pack2(qb.x, qb.y), pack2(qb.z, qb.w) };
#pragma unroll
            for (int rp = 0; rp < 4; rp++)
#pragma unroll
                for (int j = 0; j < 4; j++)
                    s2[rp][j] = fma2(q2[rp], k2[j], s2[rp][j]);
        }

        float s[8][4];
#pragma unroll
        for (int rp = 0; rp < 4; rp++)
#pragma unroll
            for (int j = 0; j < 4; j++)
                unpack2(s2[rp][j], s[2 * rp][j], s[2 * rp + 1][j]);

        if (kt >= 2 * qt) {
            const int koff = (kt - 2 * qt) * 64;
#pragma unroll
            for (int i = 0; i < 8; i++)
#pragma unroll
                for (int j = 0; j < 4; j++)
                    if (koff + tx * 4 + j > ty * 8 + i) s[i][j] = NEG_BIG;
        }

#pragma unroll
        for (int i = 0; i < 8; i++) {
            float rm = fmaxf(fmaxf(s[i][0], s[i][1]), fmaxf(s[i][2], s[i][3]));
#pragma unroll
            for (int off = 1; off < 16; off <<= 1)
                rm = fmaxf(rm, __shfl_xor_sync(0xffffffffu, rm, off));
            const float nm = fmaxf(m[i], rm);
            const float a  = __expf(m[i] - nm);
            const float p0 = __expf(s[i][0] - nm);
            const float p1 = __expf(s[i][1] - nm);
            const float p2 = __expf(s[i][2] - nm);
            const float p3 = __expf(s[i][3] - nm);
            float sum = (p0 + p1) + (p2 + p3);
#pragma unroll
            for (int off = 1; off < 16; off <<= 1)
                sum += __shfl_xor_sync(0xffffffffu, sum, off);
            l[i] = l[i] * a + sum;
            m[i] = nm;
            float4 pv; pv.x = p0; pv.y = p1; pv.z = p2; pv.w = p3;
            *(float4*)(Ps + (ty * 8 + i) * 64 + tx * 4) = pv;
            const u64 a2 = pack2(a, a);
#pragma unroll
            for (int hp = 0; hp < 4; hp++) O2[i][hp] = mul2(O2[i][hp], a2);
        }
        __syncthreads();

#pragma unroll 2
        for (int k4 = 0; k4 < 16; k4++) {
            float4 pr[8];
#pragma unroll
            for (int i = 0; i < 8; i++)
                pr[i] = *(const float4*)(Ps + (ty * 8 + i) * 64 + k4 * 4);
#pragma unroll
            for (int kk = 0; kk < 4; kk++) {
                const int k = k4 * 4 + kk;
                const float* vrow = Vs + k * 128 + tx * 8;
                float4 va = *(const float4*)(vrow);
                float4 vb = *(const float4*)(vrow + 4);
                u64 v2[4] = { pack2(va.x, va.y), pack2(va.z, va.w),
                              pack2(vb.x, vb.y), pack2(vb.z, vb.w) };
#pragma unroll
                for (int i = 0; i < 8; i++) {
                    const float pv = (kk == 0) ? pr[i].x : (kk == 1) ? pr[i].y
                                   : (kk == 2) ? pr[i].z : pr[i].w;
                    const u64 p2 = pack2(pv, pv);
#pragma unroll
                    for (int hp = 0; hp < 4; hp++)
                        O2[i][hp] = fma2(p2, v2[hp], O2[i][hp]);
                }
            }
        }
    }

    const size_t base = (size_t)(z * BATCH + b) * SEQ + q0;
#pragma unroll
    for (int i = 0; i < 8; i++) {
        const int r = ty * 8 + i;
        float* op = g_part + (base + r) * HEAD + tx * 8;
        *(u64*)(op + 0) = O2[i][0];
        *(u64*)(op + 2) = O2[i][1];
        *(u64*)(op + 4) = O2[i][2];
        *(u64*)(op + 6) = O2[i][3];
        if (tx == 0) { g_mp[base + r] = m[i]; g_lp[base + r] = l[i]; }
    }
}

// ============================================================================
// Kernel 3: merge split-K partials
// ============================================================================
__global__ __launch_bounds__(256) void combine_kernel(float* __restrict__ out)
{
    const int idx = blockIdx.x * 256 + threadIdx.x;
    const int row = idx >> 5, h4 = idx & 31;
    const float m0 = g_mp[row], m1 = g_mp[ROWS_TOTAL + row];
    const float l0 = g_lp[row], l1 = g_lp[ROWS_TOTAL + row];
    const float mm = fmaxf(m0, m1);
    const float a0 = __expf(m0 - mm), a1 = __expf(m1 - mm);
    const float inv = 1.0f / (l0 * a0 + l1 * a1);
    const float4 o0 = *(const float4*)(g_part + (size_t)row * HEAD + h4 * 4);
    const float4 o1 = *(const float4*)(g_part + ((size_t)ROWS_TOTAL + row) * HEAD + h4 * 4);
    float4 r;
    r.x = (o0.x * a0 + o1.x * a1) * inv;
    r.y = (o0.y * a0 + o1.y * a1) * inv;
    r.z = (o0.z * a0 + o1.z * a1) * inv;
    r.w = (o0.w * a0 + o1.w * a1) * inv;
    *(float4*)(out + (size_t)row * HEAD + h4 * 4) = r;
}

// ============================================================================
extern "C" void kernel_launch(void* const* d_in, const int* in_sizes, int n_in,
                              void* d_out, int out_size)
{
    const float* x  = (const float*)d_in[0];
    const float* Wq = (const float*)d_in[1];
    const float* Wk = (const float*)d_in[2];
    const float* Wv = (const float*)d_in[3];
    float* out = (float*)d_out;

    (void)cudaFuncSetAttribute(qkv_mma_kernel,
        cudaFuncAttributeMaxDynamicSharedMemorySize, QKV_SMEM);
    dim3 qgrid(ROWS_TOTAL / BM, 3);
    qkv_mma_kernel<<<qgrid, 256, QKV_SMEM>>>(x, Wq, Wk, Wv);

    (void)cudaFuncSetAttribute(attn_kernel,
        cudaFuncAttributeMaxDynamicSharedMemorySize, ATT_SMEM);
    attn_kernel<<<256, 256, ATT_SMEM>>>();

    combine_kernel<<<(ROWS_TOTAL * 32) / 256, 256>>>(out);
}

// round 10
// speedup vs baseline: 2.4856x; 1.2703x over previous
#include <cuda_runtime.h>
#include <cstdint>

#define EMBED 1024
#define HEAD  128
#define SEQ   4096
#define BATCH 4
#define ROWS_TOTAL (BATCH*SEQ)

typedef unsigned long long u64;
typedef unsigned int u32;

// scratch (device globals; no allocations allowed)
static __device__ float g_q [(size_t)ROWS_TOTAL * HEAD];
static __device__ float g_k [(size_t)ROWS_TOTAL * HEAD];    // natural [b][s][h]
static __device__ float g_v [(size_t)ROWS_TOTAL * HEAD];
static __device__ float g_part[(size_t)2 * ROWS_TOTAL * HEAD];
static __device__ float g_mp[2 * ROWS_TOTAL];
static __device__ float g_lp[2 * ROWS_TOTAL];

__device__ __forceinline__ u64 pack2(float lo, float hi) {
    u64 r; asm("mov.b64 %0, {%1, %2};" : "=l"(r) : "f"(lo), "f"(hi)); return r;
}
__device__ __forceinline__ u64 fma2(u64 a, u64 b, u64 c) {
    u64 d; asm("fma.rn.f32x2 %0, %1, %2, %3;" : "=l"(d) : "l"(a), "l"(b), "l"(c)); return d;
}
__device__ __forceinline__ u64 mul2(u64 a, u64 b) {
    u64 d; asm("mul.rn.f32x2 %0, %1, %2;" : "=l"(d) : "l"(a), "l"(b)); return d;
}
__device__ __forceinline__ u32 tf32_rna(float f) {
    u32 r; asm("cvt.rna.tf32.f32 %0, %1;" : "=r"(r) : "f"(f)); return r;
}
__device__ __forceinline__ void mma_tf32(float* d, u32 a0, u32 a1, u32 a2, u32 a3,
                                         u32 b0, u32 b1) {
    asm volatile("mma.sync.aligned.m16n8k8.row.col.f32.tf32.tf32.f32 "
        "{%0,%1,%2,%3}, {%4,%5,%6,%7}, {%8,%9}, {%0,%1,%2,%3};"
        : "+f"(d[0]), "+f"(d[1]), "+f"(d[2]), "+f"(d[3])
        : "r"(a0), "r"(a1), "r"(a2), "r"(a3), "r"(b0), "r"(b1));
}

// ============================================================================
// Kernel 1: QKV via mma.sync tf32 (proven R6; K written natural)
// ============================================================================
#define BM 128
#define BK 32
#define NCH (EMBED / BK)
#define AS_STR 36
#define BS_STR 136
#define AS_SZ (BM * AS_STR)
#define BS_SZ (BK * BS_STR)
#define QKV_SMEM ((AS_SZ + BS_SZ) * 2 * 4)

__global__ __launch_bounds__(256, 1) void qkv_mma_kernel(
    const float* __restrict__ x, const float* __restrict__ Wq,
    const float* __restrict__ Wk, const float* __restrict__ Wv)
{
    extern __shared__ __align__(16) float smq[];
    const int tid  = threadIdx.x;
    const int lane = tid & 31;
    const int wid  = tid >> 5;
    const int warp_m = (wid >> 2) * 64;
    const int warp_n = (wid & 3) * 32;
    const int m0 = blockIdx.x * BM;
    const int w  = blockIdx.y;
    const float* W = (w == 0) ? Wq : (w == 1) ? Wk : Wv;

    float* Asb[2] = { smq,         smq + AS_SZ + BS_SZ };
    float* Bsb[2] = { smq + AS_SZ, smq + 2 * AS_SZ + BS_SZ };

    float4 areg[4], breg[4];

#define LDG_CHUNK(c) do { \
    _Pragma("unroll") \
    for (int i = 0; i < 4; i++) { \
        int idx = tid + i * 256; \
        int row = idx >> 3, kq = idx & 7; \
        areg[i] = *(const float4*)(x + (size_t)(m0 + row) * EMBED + (c) * BK + kq * 4); \
        int k = idx >> 5, nq = idx & 31; \
        breg[i] = *(const float4*)(W + (size_t)((c) * BK + k) * HEAD + nq * 4); \
    } \
} while (0)

#define STS_CHUNK(buf) do { \
    _Pragma("unroll") \
    for (int i = 0; i < 4; i++) { \
        int idx = tid + i * 256; \
        int row = idx >> 3, kq = idx & 7; \
        uint4 av = { tf32_rna(areg[i].x), tf32_rna(areg[i].y), \
                     tf32_rna(areg[i].z), tf32_rna(areg[i].w) }; \
        *(uint4*)(Asb[buf] + row * AS_STR + kq * 4) = av; \
        int k = idx >> 5, nq = idx & 31; \
        uint4 bv = { tf32_rna(breg[i].x), tf32_rna(breg[i].y), \
                     tf32_rna(breg[i].z), tf32_rna(breg[i].w) }; \
        *(uint4*)(Bsb[buf] + k * BS_STR + nq * 4) = bv; \
    } \
} while (0)

    float acc[4][4][4];
#pragma unroll
    for (int mf = 0; mf < 4; mf++)
#pragma unroll
        for (int nf = 0; nf < 4; nf++)
#pragma unroll
            for (int i = 0; i < 4; i++) acc[mf][nf][i] = 0.0f;

    LDG_CHUNK(0);
    STS_CHUNK(0);
    __syncthreads();

    for (int c = 0; c < NCH; c++) {
        const int buf = c & 1;
        if (c + 1 < NCH) LDG_CHUNK(c + 1);

        const u32* ap = (const u32*)Asb[buf] + (warp_m + (lane >> 2)) * AS_STR + (lane & 3);
        const u32* bp = (const u32*)Bsb[buf] + (lane & 3) * BS_STR + warp_n + (lane >> 2);
#pragma unroll
        for (int ks = 0; ks < 4; ks++) {
            u32 a[4][4], b[4][2];
#pragma unroll
            for (int mf = 0; mf < 4; mf++) {
                const int o = mf * (16 * AS_STR) + ks * 8;
                a[mf][0] = ap[o];
                a[mf][1] = ap[o + 8 * AS_STR];
                a[mf][2] = ap[o + 4];
                a[mf][3] = ap[o + 8 * AS_STR + 4];
            }
#pragma unroll
            for (int nf = 0; nf < 4; nf++) {
                const int o = ks * (8 * BS_STR) + nf * 8;
                b[nf][0] = bp[o];
                b[nf][1] = bp[o + 4 * BS_STR];
            }
#pragma unroll
            for (int mf = 0; mf < 4; mf++)
#pragma unroll
                for (int nf = 0; nf < 4; nf++)
                    mma_tf32(acc[mf][nf], a[mf][0], a[mf][1], a[mf][2], a[mf][3],
                             b[nf][0], b[nf][1]);
        }

        if (c + 1 < NCH) {
            STS_CHUNK((c + 1) & 1);
            __syncthreads();
        }
    }

    float* dst = (w == 0) ? g_q : (w == 1) ? g_k : g_v;
#pragma unroll
    for (int mf = 0; mf < 4; mf++) {
        const int mrow = m0 + warp_m + mf * 16 + (lane >> 2);
#pragma unroll
        for (int nf = 0; nf < 4; nf++) {
            const int ncol = warp_n + nf * 8 + 2 * (lane & 3);
            float* p0 = dst + (size_t)mrow * HEAD + ncol;
            *(u64*)p0              = pack2(acc[mf][nf][0], acc[mf][nf][1]);
            *(u64*)(p0 + 8 * HEAD) = pack2(acc[mf][nf][2], acc[mf][nf][3]);
        }
    }
#undef LDG_CHUNK
#undef STS_CHUNK
}

// ============================================================================
// Kernel 2: flash attention. Scores via mma.sync tf32; AV via f32x2 SIMT.
// BQ=128, BK=64, split-K=2. 256 thr = 8 warps; warp w owns q-rows [16w,16w+16).
// ============================================================================
#define NEG_BIG (-3.0e38f)
#define M_INIT  (-1.0e30f)
#define QS_STR 132
#define KS_STR 132
#define VS_STR 128
#define PS_STR 72
#define QS_SZ (128 * QS_STR)
#define KS_SZ (64 * KS_STR)
#define VS_SZ (64 * VS_STR)
#define PS_SZ (128 * PS_STR)
#define ATT_SMEM ((QS_SZ + KS_SZ + VS_SZ + PS_SZ + 128) * 4)

__global__ __launch_bounds__(256, 1) void attn_kernel()
{
    extern __shared__ __align__(16) float smf[];
    float* Qs = smf;              // tf32 bit patterns
    float* Ks = Qs + QS_SZ;       // tf32 bit patterns
    float* Vs = Ks + KS_SZ;       // fp32
    float* Ps = Vs + VS_SZ;
    float* arow = Ps + PS_SZ;     // [128] per-row rescale factors

    const int tid  = threadIdx.x;
    const int lane = tid & 31;
    const int w    = tid >> 5;                  // warp: q-rows [16w, 16w+16)
    const int tx   = tid & 15, ty = tid >> 4;   // AV layout
    const int id = blockIdx.x;
    const int qt = 31 - (id >> 3);
    const int z  = id & 1;
    const int b  = (id >> 1) & 3;
    const int q0 = qt * 128;
    const float scale = 0.08838834764831845f;

    const int lq = lane >> 2;            // 0..7
    const int lr = lane & 3;             // 0..3

    // Q -> Qs[q][e], scaled + tf32-rounded
    {
        const float* qg = g_q + ((size_t)b * SEQ + q0) * HEAD;
#pragma unroll
        for (int i = 0; i < 16; i++) {
            int idx = tid + i * 256;
            int h4 = idx >> 7, r = idx & 127;
            float4 v = *(const float4*)(qg + (size_t)r * HEAD + h4 * 4);
            uint4 t = { tf32_rna(v.x * scale), tf32_rna(v.y * scale),
                        tf32_rna(v.z * scale), tf32_rna(v.w * scale) };
            *(uint4*)(Qs + r * QS_STR + h4 * 4) = t;
        }
    }

    u64 O2[8][4];
    float mlo = M_INIT, mhi = M_INIT, llo = 0.0f, lhi = 0.0f;
#pragma unroll
    for (int i = 0; i < 8; i++)
#pragma unroll
        for (int hp = 0; hp < 4; hp++) O2[i][hp] = 0ull;

    const int kt0 = z ? (qt + 1) : 0;
    const int kt1 = z ? (2 * qt + 2) : (qt + 1);

    for (int kt = kt0; kt < kt1; kt++) {
        __syncthreads();
        {   // K tile natural [k][e], tf32-rounded; V tile [k][h] fp32
            const float* kg = g_k + ((size_t)b * SEQ + (size_t)kt * 64) * HEAD;
            const float* vg = g_v + ((size_t)b * SEQ + (size_t)kt * 64) * HEAD;
#pragma unroll
            for (int i = 0; i < 8; i++) {
                int idx = tid + i * 256;
                int e4 = idx & 31, r = idx >> 5;
                float4 kv = *(const float4*)(kg + (size_t)r * HEAD + e4 * 4);
                uint4 t = { tf32_rna(kv.x), tf32_rna(kv.y), tf32_rna(kv.z), tf32_rna(kv.w) };
                *(uint4*)(Ks + r * KS_STR + e4 * 4) = t;
                *(float4*)(Vs + r * VS_STR + e4 * 4) =
                    *(const float4*)(vg + (size_t)r * HEAD + e4 * 4);
            }
        }
        __syncthreads();

        // ---- scores via mma: warp m16 x n64 (8 n-frags), K-loop 16 steps ----
        float acc[8][4];
#pragma unroll
        for (int nf = 0; nf < 8; nf++)
#pragma unroll
            for (int i = 0; i < 4; i++) acc[nf][i] = 0.0f;

        const u32* ap = (const u32*)Qs + (w * 16 + lq) * QS_STR + lr;
        const u32* bp = (const u32*)Ks + lq * KS_STR + lr;
#pragma unroll 2
        for (int ks = 0; ks < 16; ks++) {
            const int ko = ks * 8;
            u32 a0 = ap[ko], a1 = ap[ko + 8 * QS_STR];
            u32 a2 = ap[ko + 4], a3 = ap[ko + 8 * QS_STR + 4];
#pragma unroll
            for (int nf = 0; nf < 8; nf++) {
                const int o = nf * (8 * KS_STR) + ko;
                u32 b0 = bp[o], b1 = bp[o + 4];
                mma_tf32(acc[nf], a0, a1, a2, a3, b0, b1);
            }
        }

        // rows: rlo = 16w+lq, rhi = +8; cols: 8nf + 2lr + {0,1}
        const int rlo = w * 16 + lq, rhi = rlo + 8;
        if (kt >= 2 * qt) {
            const int koff = (kt - 2 * qt) * 64;
#pragma unroll
            for (int nf = 0; nf < 8; nf++) {
                const int c0 = koff + nf * 8 + 2 * lr;
                if (c0 > rlo)     acc[nf][0] = NEG_BIG;
                if (c0 + 1 > rlo) acc[nf][1] = NEG_BIG;
                if (c0 > rhi)     acc[nf][2] = NEG_BIG;
                if (c0 + 1 > rhi) acc[nf][3] = NEG_BIG;
            }
        }

        // ---- online softmax in frag layout (reduce over 4-lane quad) ----
        float rmlo = NEG_BIG, rmhi = NEG_BIG;
#pragma unroll
        for (int nf = 0; nf < 8; nf++) {
            rmlo = fmaxf(rmlo, fmaxf(acc[nf][0], acc[nf][1]));
            rmhi = fmaxf(rmhi, fmaxf(acc[nf][2], acc[nf][3]));
        }
#pragma unroll
        for (int off = 1; off < 4; off <<= 1) {
            rmlo = fmaxf(rmlo, __shfl_xor_sync(0xffffffffu, rmlo, off));
            rmhi = fmaxf(rmhi, __shfl_xor_sync(0xffffffffu, rmhi, off));
        }
        const float nmlo = fmaxf(mlo, rmlo), nmhi = fmaxf(mhi, rmhi);
        const float alo = __expf(mlo - nmlo), ahi = __expf(mhi - nmhi);
        float slo = 0.0f, shi = 0.0f;
#pragma unroll
        for (int nf = 0; nf < 8; nf++) {
            float p0 = __expf(acc[nf][0] - nmlo);
            float p1 = __expf(acc[nf][1] - nmlo);
            float p2 = __expf(acc[nf][2] - nmhi);
            float p3 = __expf(acc[nf][3] - nmhi);
            slo += p0 + p1; shi += p2 + p3;
            *(u64*)(Ps + rlo * PS_STR + nf * 8 + 2 * lr) = pack2(p0, p1);
            *(u64*)(Ps + rhi * PS_STR + nf * 8 + 2 * lr) = pack2(p2, p3);
        }
#pragma unroll
        for (int off = 1; off < 4; off <<= 1) {
            slo += __shfl_xor_sync(0xffffffffu, slo, off);
            shi += __shfl_xor_sync(0xffffffffu, shi, off);
        }
        llo = llo * alo + slo; mlo = nmlo;
        lhi = lhi * ahi + shi; mhi = nmhi;
        if (lr == 0) { arow[rlo] = alo; arow[rhi] = ahi; }
        __syncthreads();

        // ---- O rescale + AV (f32x2 SIMT, AV thread layout) ----
#pragma unroll
        for (int i = 0; i < 8; i++) {
            const float a = arow[ty * 8 + i];
            const u64 a2 = pack2(a, a);
#pragma unroll
            for (int hp = 0; hp < 4; hp++) O2[i][hp] = mul2(O2[i][hp], a2);
        }
#pragma unroll 2
        for (int k4 = 0; k4 < 16; k4++) {
            float4 pr[8];
#pragma unroll
            for (int i = 0; i < 8; i++)
                pr[i] = *(const float4*)(Ps + (ty * 8 + i) * PS_STR + k4 * 4);
#pragma unroll
            for (int kk = 0; kk < 4; kk++) {
                const int k = k4 * 4 + kk;
                const float* vrow = Vs + k * VS_STR + tx * 8;
                float4 va = *(const float4*)(vrow);
                float4 vb = *(const float4*)(vrow + 4);
                u64 v2[4] = { pack2(va.x, va.y), pack2(va.z, va.w),
                              pack2(vb.x, vb.y), pack2(vb.z, vb.w) };
#pragma unroll
                for (int i = 0; i < 8; i++) {
                    const float pv = (kk == 0) ? pr[i].x : (kk == 1) ? pr[i].y
                                   : (kk == 2) ? pr[i].z : pr[i].w;
                    const u64 p2 = pack2(pv, pv);
#pragma unroll
                    for (int hp = 0; hp < 4; hp++)
                        O2[i][hp] = fma2(p2, v2[hp], O2[i][hp]);
                }
            }
        }
    }

    // ---- write partials: O (AV layout), m/l (score layout) ----
    const size_t base = (size_t)(z * BATCH + b) * SEQ + q0;
#pragma unroll
    for (int i = 0; i < 8; i++) {
        const int r = ty * 8 + i;
        float* op = g_part + (base + r) * HEAD + tx * 8;
        *(u64*)(op + 0) = O2[i][0];
        *(u64*)(op + 2) = O2[i][1];
        *(u64*)(op + 4) = O2[i][2];
        *(u64*)(op + 6) = O2[i][3];
    }
    if (lr == 0) {
        const int rlo = w * 16 + lq;
        g_mp[base + rlo]     = mlo; g_lp[base + rlo]     = llo;
        g_mp[base + rlo + 8] = mhi; g_lp[base + rlo + 8] = lhi;
    }
}

// ============================================================================
// Kernel 3: merge split-K partials
// ============================================================================
__global__ __launch_bounds__(256) void combine_kernel(float* __restrict__ out)
{
    const int idx = blockIdx.x * 256 + threadIdx.x;
    const int row = idx >> 5, h4 = idx & 31;
    const float m0 = g_mp[row], m1 = g_mp[ROWS_TOTAL + row];
    const float l0 = g_lp[row], l1 = g_lp[ROWS_TOTAL + row];
    const float mm = fmaxf(m0, m1);
    const float a0 = __expf(m0 - mm), a1 = __expf(m1 - mm);
    const float inv = 1.0f / (l0 * a0 + l1 * a1);
    const float4 o0 = *(const float4*)(g_part + (size_t)row * HEAD + h4 * 4);
    const float4 o1 = *(const float4*)(g_part + ((size_t)ROWS_TOTAL + row) * HEAD + h4 * 4);
    float4 r;
    r.x = (o0.x * a0 + o1.x * a1) * inv;
    r.y = (o0.y * a0 + o1.y * a1) * inv;
    r.z = (o0.z * a0 + o1.z * a1) * inv;
    r.w = (o0.w * a0 + o1.w * a1) * inv;
    *(float4*)(out + (size_t)row * HEAD + h4 * 4) = r;
}

// ============================================================================
extern "C" void kernel_launch(void* const* d_in, const int* in_sizes, int n_in,
                              void* d_out, int out_size)
{
    const float* x  = (const float*)d_in[0];
    const float* Wq = (const float*)d_in[1];
    const float* Wk = (const float*)d_in[2];
    const float* Wv = (const float*)d_in[3];
    float* out = (float*)d_out;

    (void)cudaFuncSetAttribute(qkv_mma_kernel,
        cudaFuncAttributeMaxDynamicSharedMemorySize, QKV_SMEM);
    dim3 qgrid(ROWS_TOTAL / BM, 3);
    qkv_mma_kernel<<<qgrid, 256, QKV_SMEM>>>(x, Wq, Wk, Wv);

    (void)cudaFuncSetAttribute(attn_kernel,
        cudaFuncAttributeMaxDynamicSharedMemorySize, ATT_SMEM);
    attn_kernel<<<256, 256, ATT_SMEM>>>();

    combine_kernel<<<(ROWS_TOTAL * 32) / 256, 256>>>(out);
}

// round 11
// speedup vs baseline: 3.6092x; 1.4520x over previous
#include <cuda_runtime.h>
#include <cstdint>

#define EMBED 1024
#define HEAD  128
#define SEQ   4096
#define BATCH 4
#define ROWS_TOTAL (BATCH*SEQ)

typedef unsigned long long u64;
typedef unsigned int u32;

// scratch (device globals; no allocations allowed)
static __device__ float g_q [(size_t)ROWS_TOTAL * HEAD];
static __device__ float g_k [(size_t)ROWS_TOTAL * HEAD];    // natural [b][s][h]
static __device__ float g_vT[(size_t)BATCH * HEAD * SEQ];   // transposed [b][h][s]
static __device__ float g_part[(size_t)2 * ROWS_TOTAL * HEAD];
static __device__ float g_mp[2 * ROWS_TOTAL];
static __device__ float g_lp[2 * ROWS_TOTAL];

__device__ __forceinline__ u64 pack2(float lo, float hi) {
    u64 r; asm("mov.b64 %0, {%1, %2};" : "=l"(r) : "f"(lo), "f"(hi)); return r;
}
__device__ __forceinline__ u64 pack2u(u32 lo, u32 hi) {
    u64 r; asm("mov.b64 %0, {%1, %2};" : "=l"(r) : "r"(lo), "r"(hi)); return r;
}
__device__ __forceinline__ u32 tf32_rna(float f) {
    u32 r; asm("cvt.rna.tf32.f32 %0, %1;" : "=r"(r) : "f"(f)); return r;
}
__device__ __forceinline__ void mma_tf32(float* d, u32 a0, u32 a1, u32 a2, u32 a3,
                                         u32 b0, u32 b1) {
    asm volatile("mma.sync.aligned.m16n8k8.row.col.f32.tf32.tf32.f32 "
        "{%0,%1,%2,%3}, {%4,%5,%6,%7}, {%8,%9}, {%0,%1,%2,%3};"
        : "+f"(d[0]), "+f"(d[1]), "+f"(d[2]), "+f"(d[3])
        : "r"(a0), "r"(a1), "r"(a2), "r"(a3), "r"(b0), "r"(b1));
}

// ============================================================================
// Kernel 1: QKV via mma.sync tf32 (proven). V now written TRANSPOSED.
// ============================================================================
#define BM 128
#define BK 32
#define NCH (EMBED / BK)
#define AS_STR 36
#define BS_STR 136
#define AS_SZ (BM * AS_STR)
#define BS_SZ (BK * BS_STR)
#define QKV_SMEM ((AS_SZ + BS_SZ) * 2 * 4)

__global__ __launch_bounds__(256, 1) void qkv_mma_kernel(
    const float* __restrict__ x, const float* __restrict__ Wq,
    const float* __restrict__ Wk, const float* __restrict__ Wv)
{
    extern __shared__ __align__(16) float smq[];
    const int tid  = threadIdx.x;
    const int lane = tid & 31;
    const int wid  = tid >> 5;
    const int warp_m = (wid >> 2) * 64;
    const int warp_n = (wid & 3) * 32;
    const int m0 = blockIdx.x * BM;
    const int w  = blockIdx.y;
    const float* W = (w == 0) ? Wq : (w == 1) ? Wk : Wv;

    float* Asb[2] = { smq,         smq + AS_SZ + BS_SZ };
    float* Bsb[2] = { smq + AS_SZ, smq + 2 * AS_SZ + BS_SZ };

    float4 areg[4], breg[4];

#define LDG_CHUNK(c) do { \
    _Pragma("unroll") \
    for (int i = 0; i < 4; i++) { \
        int idx = tid + i * 256; \
        int row = idx >> 3, kq = idx & 7; \
        areg[i] = *(const float4*)(x + (size_t)(m0 + row) * EMBED + (c) * BK + kq * 4); \
        int k = idx >> 5, nq = idx & 31; \
        breg[i] = *(const float4*)(W + (size_t)((c) * BK + k) * HEAD + nq * 4); \
    } \
} while (0)

#define STS_CHUNK(buf) do { \
    _Pragma("unroll") \
    for (int i = 0; i < 4; i++) { \
        int idx = tid + i * 256; \
        int row = idx >> 3, kq = idx & 7; \
        uint4 av = { tf32_rna(areg[i].x), tf32_rna(areg[i].y), \
                     tf32_rna(areg[i].z), tf32_rna(areg[i].w) }; \
        *(uint4*)(Asb[buf] + row * AS_STR + kq * 4) = av; \
        int k = idx >> 5, nq = idx & 31; \
        uint4 bv = { tf32_rna(breg[i].x), tf32_rna(breg[i].y), \
                     tf32_rna(breg[i].z), tf32_rna(breg[i].w) }; \
        *(uint4*)(Bsb[buf] + k * BS_STR + nq * 4) = bv; \
    } \
} while (0)

    float acc[4][4][4];
#pragma unroll
    for (int mf = 0; mf < 4; mf++)
#pragma unroll
        for (int nf = 0; nf < 4; nf++)
#pragma unroll
            for (int i = 0; i < 4; i++) acc[mf][nf][i] = 0.0f;

    LDG_CHUNK(0);
    STS_CHUNK(0);
    __syncthreads();

    for (int c = 0; c < NCH; c++) {
        const int buf = c & 1;
        if (c + 1 < NCH) LDG_CHUNK(c + 1);

        const u32* ap = (const u32*)Asb[buf] + (warp_m + (lane >> 2)) * AS_STR + (lane & 3);
        const u32* bp = (const u32*)Bsb[buf] + (lane & 3) * BS_STR + warp_n + (lane >> 2);
#pragma unroll
        for (int ks = 0; ks < 4; ks++) {
            u32 a[4][4], b[4][2];
#pragma unroll
            for (int mf = 0; mf < 4; mf++) {
                const int o = mf * (16 * AS_STR) + ks * 8;
                a[mf][0] = ap[o];
                a[mf][1] = ap[o + 8 * AS_STR];
                a[mf][2] = ap[o + 4];
                a[mf][3] = ap[o + 8 * AS_STR + 4];
            }
#pragma unroll
            for (int nf = 0; nf < 4; nf++) {
                const int o = ks * (8 * BS_STR) + nf * 8;
                b[nf][0] = bp[o];
                b[nf][1] = bp[o + 4 * BS_STR];
            }
#pragma unroll
            for (int mf = 0; mf < 4; mf++)
#pragma unroll
                for (int nf = 0; nf < 4; nf++)
                    mma_tf32(acc[mf][nf], a[mf][0], a[mf][1], a[mf][2], a[mf][3],
                             b[nf][0], b[nf][1]);
        }

        if (c + 1 < NCH) {
            STS_CHUNK((c + 1) & 1);
            __syncthreads();
        }
    }

#pragma unroll
    for (int mf = 0; mf < 4; mf++) {
        const int mrow = m0 + warp_m + mf * 16 + (lane >> 2);
#pragma unroll
        for (int nf = 0; nf < 4; nf++) {
            const int ncol = warp_n + nf * 8 + 2 * (lane & 3);
            if (w == 2) {   // V -> transposed g_vT[b][h][s]
                const int b0 = mrow >> 12, rb = mrow & (SEQ - 1);
                float* vp = g_vT + ((size_t)b0 * HEAD + ncol) * SEQ + rb;
                vp[0]       = acc[mf][nf][0];
                vp[SEQ]     = acc[mf][nf][1];
                vp[8]       = acc[mf][nf][2];
                vp[SEQ + 8] = acc[mf][nf][3];
            } else {
                float* dst = (w == 0) ? g_q : g_k;
                float* p0 = dst + (size_t)mrow * HEAD + ncol;
                *(u64*)p0              = pack2(acc[mf][nf][0], acc[mf][nf][1]);
                *(u64*)(p0 + 8 * HEAD) = pack2(acc[mf][nf][2], acc[mf][nf][3]);
            }
        }
    }
#undef LDG_CHUNK
#undef STS_CHUNK
}

// ============================================================================
// Kernel 2: flash attention, scores AND AV via mma.sync tf32.
// BQ=128, BK=64, split-K=2. 8 warps; warp w owns q-rows [16w,16w+16) for
// BOTH gemms (no cross-warp P handoff; __syncwarp only).
// Qs[q][e] str 132, Ks[k][e] str 132, Vs[h][k] str 68, Ps[q][k] str 68 (tf32).
// ============================================================================
#define NEG_BIG (-3.0e38f)
#define M_INIT  (-1.0e30f)
#define QS_STR 132
#define KS_STR 132
#define VS_STR 68
#define PS_STR 68
#define QS_SZ (128 * QS_STR)
#define KS_SZ (64 * KS_STR)
#define VS_SZ (128 * VS_STR)
#define PS_SZ (128 * PS_STR)
#define ATT_SMEM ((QS_SZ + KS_SZ + VS_SZ + PS_SZ) * 4)

__global__ __launch_bounds__(256, 1) void attn_kernel()
{
    extern __shared__ __align__(16) float smf[];
    float* Qs = smf;              // tf32 bits
    float* Ks = Qs + QS_SZ;       // tf32 bits
    float* Vs = Ks + KS_SZ;       // tf32 bits, [h][k]
    float* Ps = Vs + VS_SZ;       // tf32 bits, [q][k]

    const int tid  = threadIdx.x;
    const int lane = tid & 31;
    const int w    = tid >> 5;
    const int id = blockIdx.x;
    const int qt = 31 - (id >> 3);
    const int z  = id & 1;
    const int b  = (id >> 1) & 3;
    const int q0 = qt * 128;
    const float scale = 0.08838834764831845f;

    const int lq = lane >> 2;            // 0..7
    const int lr = lane & 3;             // 0..3
    const int rlo = w * 16 + lq, rhi = rlo + 8;

    // Q -> Qs[q][e], scaled + tf32-rounded
    {
        const float* qg = g_q + ((size_t)b * SEQ + q0) * HEAD;
#pragma unroll
        for (int i = 0; i < 16; i++) {
            int idx = tid + i * 256;
            int h4 = idx >> 7, r = idx & 127;
            float4 v = *(const float4*)(qg + (size_t)r * HEAD + h4 * 4);
            uint4 t = { tf32_rna(v.x * scale), tf32_rna(v.y * scale),
                        tf32_rna(v.z * scale), tf32_rna(v.w * scale) };
            *(uint4*)(Qs + r * QS_STR + h4 * 4) = t;
        }
    }

    float O[16][4];                      // C-frag layout: rows rlo/rhi, 16 h-frags
#pragma unroll
    for (int nf = 0; nf < 16; nf++)
#pragma unroll
        for (int i = 0; i < 4; i++) O[nf][i] = 0.0f;
    float mlo = M_INIT, mhi = M_INIT, llo = 0.0f, lhi = 0.0f;

    const int kt0 = z ? (qt + 1) : 0;
    const int kt1 = z ? (2 * qt + 2) : (qt + 1);

    for (int kt = kt0; kt < kt1; kt++) {
        __syncthreads();
        {   // K tile [k][e] (tf32); V^T tile [h][k] (tf32), coalesced from g_vT
            const float* kg = g_k + ((size_t)b * SEQ + (size_t)kt * 64) * HEAD;
            const float* vg = g_vT + (size_t)b * HEAD * SEQ + (size_t)kt * 64;
#pragma unroll
            for (int i = 0; i < 8; i++) {
                int idx = tid + i * 256;
                int e4 = idx & 31, r = idx >> 5;
                float4 kv = *(const float4*)(kg + (size_t)r * HEAD + e4 * 4);
                uint4 t = { tf32_rna(kv.x), tf32_rna(kv.y), tf32_rna(kv.z), tf32_rna(kv.w) };
                *(uint4*)(Ks + r * KS_STR + e4 * 4) = t;
                int h = idx >> 4, k4 = idx & 15;
                float4 vv = *(const float4*)(vg + (size_t)h * SEQ + k4 * 4);
                uint4 tv = { tf32_rna(vv.x), tf32_rna(vv.y), tf32_rna(vv.z), tf32_rna(vv.w) };
                *(uint4*)(Vs + h * VS_STR + k4 * 4) = tv;
            }
        }
        __syncthreads();

        // ---- scores: warp m16 x n64 ----
        float acc[8][4];
#pragma unroll
        for (int nf = 0; nf < 8; nf++)
#pragma unroll
            for (int i = 0; i < 4; i++) acc[nf][i] = 0.0f;

        const u32* ap = (const u32*)Qs + rlo * QS_STR + lr;
        const u32* bp = (const u32*)Ks + lq * KS_STR + lr;
#pragma unroll 2
        for (int ks = 0; ks < 16; ks++) {
            const int ko = ks * 8;
            u32 a0 = ap[ko], a1 = ap[ko + 8 * QS_STR];
            u32 a2 = ap[ko + 4], a3 = ap[ko + 8 * QS_STR + 4];
#pragma unroll
            for (int nf = 0; nf < 8; nf++) {
                const int o = nf * (8 * KS_STR) + ko;
                mma_tf32(acc[nf], a0, a1, a2, a3, bp[o], bp[o + 4]);
            }
        }

        if (kt >= 2 * qt) {
            const int koff = (kt - 2 * qt) * 64;
#pragma unroll
            for (int nf = 0; nf < 8; nf++) {
                const int c0 = koff + nf * 8 + 2 * lr;
                if (c0 > rlo)     acc[nf][0] = NEG_BIG;
                if (c0 + 1 > rlo) acc[nf][1] = NEG_BIG;
                if (c0 > rhi)     acc[nf][2] = NEG_BIG;
                if (c0 + 1 > rhi) acc[nf][3] = NEG_BIG;
            }
        }

        // ---- online softmax (quad reduction) ----
        float rmlo = NEG_BIG, rmhi = NEG_BIG;
#pragma unroll
        for (int nf = 0; nf < 8; nf++) {
            rmlo = fmaxf(rmlo, fmaxf(acc[nf][0], acc[nf][1]));
            rmhi = fmaxf(rmhi, fmaxf(acc[nf][2], acc[nf][3]));
        }
#pragma unroll
        for (int off = 1; off < 4; off <<= 1) {
            rmlo = fmaxf(rmlo, __shfl_xor_sync(0xffffffffu, rmlo, off));
            rmhi = fmaxf(rmhi, __shfl_xor_sync(0xffffffffu, rmhi, off));
        }
        const float nmlo = fmaxf(mlo, rmlo), nmhi = fmaxf(mhi, rmhi);
        const float alo = __expf(mlo - nmlo), ahi = __expf(mhi - nmhi);
        float slo = 0.0f, shi = 0.0f;
#pragma unroll
        for (int nf = 0; nf < 8; nf++) {
            float p0 = __expf(acc[nf][0] - nmlo);
            float p1 = __expf(acc[nf][1] - nmlo);
            float p2 = __expf(acc[nf][2] - nmhi);
            float p3 = __expf(acc[nf][3] - nmhi);
            slo += p0 + p1; shi += p2 + p3;
            *(u64*)(Ps + rlo * PS_STR + nf * 8 + 2 * lr) = pack2u(tf32_rna(p0), tf32_rna(p1));
            *(u64*)(Ps + rhi * PS_STR + nf * 8 + 2 * lr) = pack2u(tf32_rna(p2), tf32_rna(p3));
        }
#pragma unroll
        for (int off = 1; off < 4; off <<= 1) {
            slo += __shfl_xor_sync(0xffffffffu, slo, off);
            shi += __shfl_xor_sync(0xffffffffu, shi, off);
        }
        llo = llo * alo + slo; mlo = nmlo;
        lhi = lhi * ahi + shi; mhi = nmhi;
        __syncwarp();

        // ---- O rescale + AV via mma: warp m16 x n128 (16 h-frags) ----
#pragma unroll
        for (int nf = 0; nf < 16; nf++) {
            O[nf][0] *= alo; O[nf][1] *= alo;
            O[nf][2] *= ahi; O[nf][3] *= ahi;
        }
        const u32* pa = (const u32*)Ps + rlo * PS_STR + lr;
        const u32* vb = (const u32*)Vs + lq * VS_STR + lr;
#pragma unroll
        for (int ks = 0; ks < 8; ks++) {
            const int ko = ks * 8;
            u32 a0 = pa[ko], a1 = pa[ko + 8 * PS_STR];
            u32 a2 = pa[ko + 4], a3 = pa[ko + 8 * PS_STR + 4];
#pragma unroll
            for (int nf = 0; nf < 16; nf++) {
                const int o = nf * (8 * VS_STR) + ko;
                mma_tf32(O[nf], a0, a1, a2, a3, vb[o], vb[o + 4]);
            }
        }
    }

    // ---- write partials (C-frag layout) ----
    const size_t base = (size_t)(z * BATCH + b) * SEQ + q0;
    float* oplo = g_part + (base + rlo) * HEAD + 2 * lr;
    float* ophi = g_part + (base + rhi) * HEAD + 2 * lr;
#pragma unroll
    for (int nf = 0; nf < 16; nf++) {
        *(u64*)(oplo + nf * 8) = pack2(O[nf][0], O[nf][1]);
        *(u64*)(ophi + nf * 8) = pack2(O[nf][2], O[nf][3]);
    }
    if (lr == 0) {
        g_mp[base + rlo] = mlo; g_lp[base + rlo] = llo;
        g_mp[base + rhi] = mhi; g_lp[base + rhi] = lhi;
    }
}

// ============================================================================
// Kernel 3: merge split-K partials
// ============================================================================
__global__ __launch_bounds__(256) void combine_kernel(float* __restrict__ out)
{
    const int idx = blockIdx.x * 256 + threadIdx.x;
    const int row = idx >> 5, h4 = idx & 31;
    const float m0 = g_mp[row], m1 = g_mp[ROWS_TOTAL + row];
    const float l0 = g_lp[row], l1 = g_lp[ROWS_TOTAL + row];
    const float mm = fmaxf(m0, m1);
    const float a0 = __expf(m0 - mm), a1 = __expf(m1 - mm);
    const float inv = 1.0f / (l0 * a0 + l1 * a1);
    const float4 o0 = *(const float4*)(g_part + (size_t)row * HEAD + h4 * 4);
    const float4 o1 = *(const float4*)(g_part + ((size_t)ROWS_TOTAL + row) * HEAD + h4 * 4);
    float4 r;
    r.x = (o0.x * a0 + o1.x * a1) * inv;
    r.y = (o0.y * a0 + o1.y * a1) * inv;
    r.z = (o0.z * a0 + o1.z * a1) * inv;
    r.w = (o0.w * a0 + o1.w * a1) * inv;
    *(float4*)(out + (size_t)row * HEAD + h4 * 4) = r;
}

// ============================================================================
extern "C" void kernel_launch(void* const* d_in, const int* in_sizes, int n_in,
                              void* d_out, int out_size)
{
    const float* x  = (const float*)d_in[0];
    const float* Wq = (const float*)d_in[1];
    const float* Wk = (const float*)d_in[2];
    const float* Wv = (const float*)d_in[3];
    float* out = (float*)d_out;

    (void)cudaFuncSetAttribute(qkv_mma_kernel,
        cudaFuncAttributeMaxDynamicSharedMemorySize, QKV_SMEM);
    dim3 qgrid(ROWS_TOTAL / BM, 3);
    qkv_mma_kernel<<<qgrid, 256, QKV_SMEM>>>(x, Wq, Wk, Wv);

    (void)cudaFuncSetAttribute(attn_kernel,
        cudaFuncAttributeMaxDynamicSharedMemorySize, ATT_SMEM);
    attn_kernel<<<256, 256, ATT_SMEM>>>();

    combine_kernel<<<(ROWS_TOTAL * 32) / 256, 256>>>(out);
}

// round 12
// speedup vs baseline: 3.6588x; 1.0137x over previous
#include <cuda_runtime.h>
#include <cstdint>

#define EMBED 1024
#define HEAD  128
#define SEQ   4096
#define BATCH 4
#define ROWS_TOTAL (BATCH*SEQ)

typedef unsigned long long u64;
typedef unsigned int u32;

// scratch (device globals; no allocations allowed)
static __device__ float g_q [(size_t)ROWS_TOTAL * HEAD];    // [b][s][h'] h-interleaved
static __device__ float g_k [(size_t)ROWS_TOTAL * HEAD];    // [b][s][h'] h-interleaved
static __device__ float g_vT[(size_t)BATCH * HEAD * SEQ];   // [b][h][s'] s-interleaved
static __device__ float g_part[(size_t)2 * ROWS_TOTAL * HEAD];
static __device__ float g_mp[2 * ROWS_TOTAL];
static __device__ float g_lp[2 * ROWS_TOTAL];

__device__ __forceinline__ u64 pack2(float lo, float hi) {
    u64 r; asm("mov.b64 %0, {%1, %2};" : "=l"(r) : "f"(lo), "f"(hi)); return r;
}
__device__ __forceinline__ void unpk(u64 v, u32& lo, u32& hi) {
    asm("mov.b64 {%0, %1}, %2;" : "=r"(lo), "=r"(hi) : "l"(v));
}
__device__ __forceinline__ u32 tf32_rna(float f) {
    u32 r; asm("cvt.rna.tf32.f32 %0, %1;" : "=r"(r) : "f"(f)); return r;
}
// contracted-dim interleave within groups of 8: logical j -> physical
__device__ __forceinline__ int p8(int j) { return (j < 4) ? (j << 1) : (((j - 4) << 1) | 1); }

__device__ __forceinline__ void mma_tf32(float* d, u32 a0, u32 a1, u32 a2, u32 a3,
                                         u32 b0, u32 b1) {
    asm volatile("mma.sync.aligned.m16n8k8.row.col.f32.tf32.tf32.f32 "
        "{%0,%1,%2,%3}, {%4,%5,%6,%7}, {%8,%9}, {%0,%1,%2,%3};"
        : "+f"(d[0]), "+f"(d[1]), "+f"(d[2]), "+f"(d[3])
        : "r"(a0), "r"(a1), "r"(a2), "r"(a3), "r"(b0), "r"(b1));
}

// ============================================================================
// Kernel 1: QKV via mma.sync tf32 (proven mainloop, untouched).
// Epilogue: Q,K written with h-interleave; V written transposed with s-interleave.
// ============================================================================
#define BM 128
#define BK 32
#define NCH (EMBED / BK)
#define AS_STR 36
#define BS_STR 136
#define AS_SZ (BM * AS_STR)
#define BS_SZ (BK * BS_STR)
#define QKV_SMEM ((AS_SZ + BS_SZ) * 2 * 4)

__global__ __launch_bounds__(256, 1) void qkv_mma_kernel(
    const float* __restrict__ x, const float* __restrict__ Wq,
    const float* __restrict__ Wk, const float* __restrict__ Wv)
{
    extern __shared__ __align__(16) float smq[];
    const int tid  = threadIdx.x;
    const int lane = tid & 31;
    const int wid  = tid >> 5;
    const int warp_m = (wid >> 2) * 64;
    const int warp_n = (wid & 3) * 32;
    const int m0 = blockIdx.x * BM;
    const int w  = blockIdx.y;
    const float* W = (w == 0) ? Wq : (w == 1) ? Wk : Wv;

    float* Asb[2] = { smq,         smq + AS_SZ + BS_SZ };
    float* Bsb[2] = { smq + AS_SZ, smq + 2 * AS_SZ + BS_SZ };

    float4 areg[4], breg[4];

#define LDG_CHUNK(c) do { \
    _Pragma("unroll") \
    for (int i = 0; i < 4; i++) { \
        int idx = tid + i * 256; \
        int row = idx >> 3, kq = idx & 7; \
        areg[i] = *(const float4*)(x + (size_t)(m0 + row) * EMBED + (c) * BK + kq * 4); \
        int k = idx >> 5, nq = idx & 31; \
        breg[i] = *(const float4*)(W + (size_t)((c) * BK + k) * HEAD + nq * 4); \
    } \
} while (0)

#define STS_CHUNK(buf) do { \
    _Pragma("unroll") \
    for (int i = 0; i < 4; i++) { \
        int idx = tid + i * 256; \
        int row = idx >> 3, kq = idx & 7; \
        uint4 av = { tf32_rna(areg[i].x), tf32_rna(areg[i].y), \
                     tf32_rna(areg[i].z), tf32_rna(areg[i].w) }; \
        *(uint4*)(Asb[buf] + row * AS_STR + kq * 4) = av; \
        int k = idx >> 5, nq = idx & 31; \
        uint4 bv = { tf32_rna(breg[i].x), tf32_rna(breg[i].y), \
                     tf32_rna(breg[i].z), tf32_rna(breg[i].w) }; \
        *(uint4*)(Bsb[buf] + k * BS_STR + nq * 4) = bv; \
    } \
} while (0)

    float acc[4][4][4];
#pragma unroll
    for (int mf = 0; mf < 4; mf++)
#pragma unroll
        for (int nf = 0; nf < 4; nf++)
#pragma unroll
            for (int i = 0; i < 4; i++) acc[mf][nf][i] = 0.0f;

    LDG_CHUNK(0);
    STS_CHUNK(0);
    __syncthreads();

    for (int c = 0; c < NCH; c++) {
        const int buf = c & 1;
        if (c + 1 < NCH) LDG_CHUNK(c + 1);

        const u32* ap = (const u32*)Asb[buf] + (warp_m + (lane >> 2)) * AS_STR + (lane & 3);
        const u32* bp = (const u32*)Bsb[buf] + (lane & 3) * BS_STR + warp_n + (lane >> 2);
#pragma unroll
        for (int ks = 0; ks < 4; ks++) {
            u32 a[4][4], b[4][2];
#pragma unroll
            for (int mf = 0; mf < 4; mf++) {
                const int o = mf * (16 * AS_STR) + ks * 8;
                a[mf][0] = ap[o];
                a[mf][1] = ap[o + 8 * AS_STR];
                a[mf][2] = ap[o + 4];
                a[mf][3] = ap[o + 8 * AS_STR + 4];
            }
#pragma unroll
            for (int nf = 0; nf < 4; nf++) {
                const int o = ks * (8 * BS_STR) + nf * 8;
                b[nf][0] = bp[o];
                b[nf][1] = bp[o + 4 * BS_STR];
            }
#pragma unroll
            for (int mf = 0; mf < 4; mf++)
#pragma unroll
                for (int nf = 0; nf < 4; nf++)
                    mma_tf32(acc[mf][nf], a[mf][0], a[mf][1], a[mf][2], a[mf][3],
                             b[nf][0], b[nf][1]);
        }

        if (c + 1 < NCH) {
            STS_CHUNK((c + 1) & 1);
            __syncthreads();
        }
    }

    const int lr = lane & 3;
    const int g0 = p8(2 * lr), g1 = p8(2 * lr + 1);   // interleaved in-group cols
#pragma unroll
    for (int mf = 0; mf < 4; mf++) {
        const int mrow = m0 + warp_m + mf * 16 + (lane >> 2);
#pragma unroll
        for (int nf = 0; nf < 4; nf++) {
            const int nbase = warp_n + nf * 8;
            if (w == 2) {   // V -> transposed g_vT[b][h][s'], s interleaved
                const int b0 = mrow >> 12, rb = mrow & (SEQ - 1);
                const int rbp = (rb & ~7) | p8(rb & 7);
                float* vp = g_vT + ((size_t)b0 * HEAD + nbase + 2 * lr) * SEQ + rbp;
                vp[0]       = acc[mf][nf][0];
                vp[SEQ]     = acc[mf][nf][1];
                vp[8]       = acc[mf][nf][2];
                vp[SEQ + 8] = acc[mf][nf][3];
            } else {        // Q/K natural rows, h interleaved within 8-groups
                float* dst = (w == 0) ? g_q : g_k;
                float* p0 = dst + (size_t)mrow * HEAD + nbase;
                p0[g0]            = acc[mf][nf][0];
                p0[g1]            = acc[mf][nf][1];
                p0[g0 + 8 * HEAD] = acc[mf][nf][2];
                p0[g1 + 8 * HEAD] = acc[mf][nf][3];
            }
        }
    }
#undef LDG_CHUNK
#undef STS_CHUNK
}

// ============================================================================
// Kernel 2: flash attention, scores + AV via mma.sync tf32.
// Contracted dims pre-interleaved -> ALL frag loads are LDS.64.
// Strides 136/72 (== 8 mod 32): conflict-free LDS.64 per half-warp.
// ============================================================================
#define NEG_BIG (-3.0e38f)
#define M_INIT  (-1.0e30f)
#define QS_STR 136
#define KS_STR 136
#define VS_STR 72
#define PS_STR 72
#define QS_SZ (128 * QS_STR)
#define KS_SZ (64 * KS_STR)
#define VS_SZ (128 * VS_STR)
#define PS_SZ (128 * PS_STR)
#define ATT_SMEM ((QS_SZ + KS_SZ + VS_SZ + PS_SZ) * 4)

__global__ __launch_bounds__(256, 1) void attn_kernel()
{
    extern __shared__ __align__(16) float smf[];
    float* Qs = smf;              // tf32 bits, [q][e'] e-interleaved
    float* Ks = Qs + QS_SZ;       // tf32 bits, [k][e'] e-interleaved
    float* Vs = Ks + KS_SZ;       // tf32 bits, [h][s'] s-interleaved
    float* Ps = Vs + VS_SZ;       // tf32 bits, [q][s'] s-interleaved

    const int tid  = threadIdx.x;
    const int lane = tid & 31;
    const int w    = tid >> 5;
    const int id = blockIdx.x;
    const int qt = 31 - (id >> 3);
    const int z  = id & 1;
    const int b  = (id >> 1) & 3;
    const int q0 = qt * 128;
    const float scale = 0.08838834764831845f;

    const int lq = lane >> 2;            // 0..7
    const int lr = lane & 3;             // 0..3
    const int rlo = w * 16 + lq, rhi = rlo + 8;
    const int g0 = p8(2 * lr), g1 = p8(2 * lr + 1);

    // Q -> Qs[q][e'], scaled + tf32-rounded (gmem already h-interleaved)
    {
        const float* qg = g_q + ((size_t)b * SEQ + q0) * HEAD;
#pragma unroll
        for (int i = 0; i < 16; i++) {
            int idx = tid + i * 256;
            int h4 = idx >> 7, r = idx & 127;
            float4 v = *(const float4*)(qg + (size_t)r * HEAD + h4 * 4);
            uint4 t = { tf32_rna(v.x * scale), tf32_rna(v.y * scale),
                        tf32_rna(v.z * scale), tf32_rna(v.w * scale) };
            *(uint4*)(Qs + r * QS_STR + h4 * 4) = t;
        }
    }

    float O[16][4];
#pragma unroll
    for (int nf = 0; nf < 16; nf++)
#pragma unroll
        for (int i = 0; i < 4; i++) O[nf][i] = 0.0f;
    float mlo = M_INIT, mhi = M_INIT, llo = 0.0f, lhi = 0.0f;

    const int kt0 = z ? (qt + 1) : 0;
    const int kt1 = z ? (2 * qt + 2) : (qt + 1);

    for (int kt = kt0; kt < kt1; kt++) {
        __syncthreads();
        {   // K tile [k][e'] (tf32); V^T tile [h][s'] (tf32)
            const float* kg = g_k + ((size_t)b * SEQ + (size_t)kt * 64) * HEAD;
            const float* vg = g_vT + (size_t)b * HEAD * SEQ + (size_t)kt * 64;
#pragma unroll
            for (int i = 0; i < 8; i++) {
                int idx = tid + i * 256;
                int e4 = idx & 31, r = idx >> 5;
                float4 kv = *(const float4*)(kg + (size_t)r * HEAD + e4 * 4);
                uint4 t = { tf32_rna(kv.x), tf32_rna(kv.y), tf32_rna(kv.z), tf32_rna(kv.w) };
                *(uint4*)(Ks + r * KS_STR + e4 * 4) = t;
                int h = idx >> 4, k4 = idx & 15;
                float4 vv = *(const float4*)(vg + (size_t)h * SEQ + k4 * 4);
                uint4 tv = { tf32_rna(vv.x), tf32_rna(vv.y), tf32_rna(vv.z), tf32_rna(vv.w) };
                *(uint4*)(Vs + h * VS_STR + k4 * 4) = tv;
            }
        }
        __syncthreads();

        // ---- scores: warp m16 x n64, all frag loads LDS.64 ----
        float acc[8][4];
#pragma unroll
        for (int nf = 0; nf < 8; nf++)
#pragma unroll
            for (int i = 0; i < 4; i++) acc[nf][i] = 0.0f;

        const u32* apl = (const u32*)Qs + rlo * QS_STR + 2 * lr;
        const u32* aph = (const u32*)Qs + rhi * QS_STR + 2 * lr;
        const u32* bp  = (const u32*)Ks + lq * KS_STR + 2 * lr;
#pragma unroll 2
        for (int ks = 0; ks < 16; ks++) {
            const int ko = ks * 8;
            u32 a0, a1, a2, a3;
            unpk(*(const u64*)(apl + ko), a0, a2);
            unpk(*(const u64*)(aph + ko), a1, a3);
#pragma unroll
            for (int nf = 0; nf < 8; nf++) {
                u32 b0, b1;
                unpk(*(const u64*)(bp + nf * (8 * KS_STR) + ko), b0, b1);
                mma_tf32(acc[nf], a0, a1, a2, a3, b0, b1);
            }
        }

        if (kt >= 2 * qt) {
            const int koff = (kt - 2 * qt) * 64;
#pragma unroll
            for (int nf = 0; nf < 8; nf++) {
                const int c0 = koff + nf * 8 + 2 * lr;
                if (c0 > rlo)     acc[nf][0] = NEG_BIG;
                if (c0 + 1 > rlo) acc[nf][1] = NEG_BIG;
                if (c0 > rhi)     acc[nf][2] = NEG_BIG;
                if (c0 + 1 > rhi) acc[nf][3] = NEG_BIG;
            }
        }

        // ---- online softmax (quad reduction) ----
        float rmlo = NEG_BIG, rmhi = NEG_BIG;
#pragma unroll
        for (int nf = 0; nf < 8; nf++) {
            rmlo = fmaxf(rmlo, fmaxf(acc[nf][0], acc[nf][1]));
            rmhi = fmaxf(rmhi, fmaxf(acc[nf][2], acc[nf][3]));
        }
#pragma unroll
        for (int off = 1; off < 4; off <<= 1) {
            rmlo = fmaxf(rmlo, __shfl_xor_sync(0xffffffffu, rmlo, off));
            rmhi = fmaxf(rmhi, __shfl_xor_sync(0xffffffffu, rmhi, off));
        }
        const float nmlo = fmaxf(mlo, rmlo), nmhi = fmaxf(mhi, rmhi);
        const float alo = __expf(mlo - nmlo), ahi = __expf(mhi - nmhi);
        float slo = 0.0f, shi = 0.0f;
        u32* PsU = (u32*)Ps;
#pragma unroll
        for (int nf = 0; nf < 8; nf++) {
            float p0 = __expf(acc[nf][0] - nmlo);
            float p1 = __expf(acc[nf][1] - nmlo);
            float p2 = __expf(acc[nf][2] - nmhi);
            float p3 = __expf(acc[nf][3] - nmhi);
            slo += p0 + p1; shi += p2 + p3;
            PsU[rlo * PS_STR + nf * 8 + g0] = tf32_rna(p0);
            PsU[rlo * PS_STR + nf * 8 + g1] = tf32_rna(p1);
            PsU[rhi * PS_STR + nf * 8 + g0] = tf32_rna(p2);
            PsU[rhi * PS_STR + nf * 8 + g1] = tf32_rna(p3);
        }
#pragma unroll
        for (int off = 1; off < 4; off <<= 1) {
            slo += __shfl_xor_sync(0xffffffffu, slo, off);
            shi += __shfl_xor_sync(0xffffffffu, shi, off);
        }
        llo = llo * alo + slo; mlo = nmlo;
        lhi = lhi * ahi + shi; mhi = nmhi;
        __syncwarp();

        // ---- O rescale + AV: warp m16 x n128, all frag loads LDS.64 ----
#pragma unroll
        for (int nf = 0; nf < 16; nf++) {
            O[nf][0] *= alo; O[nf][1] *= alo;
            O[nf][2] *= ahi; O[nf][3] *= ahi;
        }
        const u32* pal = (const u32*)Ps + rlo * PS_STR + 2 * lr;
        const u32* pah = (const u32*)Ps + rhi * PS_STR + 2 * lr;
        const u32* vb  = (const u32*)Vs + lq * VS_STR + 2 * lr;
#pragma unroll 2
        for (int ks = 0; ks < 8; ks++) {
            const int ko = ks * 8;
            u32 a0, a1, a2, a3;
            unpk(*(const u64*)(pal + ko), a0, a2);
            unpk(*(const u64*)(pah + ko), a1, a3);
#pragma unroll
            for (int nf = 0; nf < 16; nf++) {
                u32 b0, b1;
                unpk(*(const u64*)(vb + nf * (8 * VS_STR) + ko), b0, b1);
                mma_tf32(O[nf], a0, a1, a2, a3, b0, b1);
            }
        }
    }

    // ---- write partials (C-frag layout; h natural) ----
    const size_t base = (size_t)(z * BATCH + b) * SEQ + q0;
    float* oplo = g_part + (base + rlo) * HEAD + 2 * lr;
    float* ophi = g_part + (base + rhi) * HEAD + 2 * lr;
#pragma unroll
    for (int nf = 0; nf < 16; nf++) {
        *(u64*)(oplo + nf * 8) = pack2(O[nf][0], O[nf][1]);
        *(u64*)(ophi + nf * 8) = pack2(O[nf][2], O[nf][3]);
    }
    if (lr == 0) {
        g_mp[base + rlo] = mlo; g_lp[base + rlo] = llo;
        g_mp[base + rhi] = mhi; g_lp[base + rhi] = lhi;
    }
}

// ============================================================================
// Kernel 3: merge split-K partials
// ============================================================================
__global__ __launch_bounds__(256) void combine_kernel(float* __restrict__ out)
{
    const int idx = blockIdx.x * 256 + threadIdx.x;
    const int row = idx >> 5, h4 = idx & 31;
    const float m0 = g_mp[row], m1 = g_mp[ROWS_TOTAL + row];
    const float l0 = g_lp[row], l1 = g_lp[ROWS_TOTAL + row];
    const float mm = fmaxf(m0, m1);
    const float a0 = __expf(m0 - mm), a1 = __expf(m1 - mm);
    const float inv = 1.0f / (l0 * a0 + l1 * a1);
    const float4 o0 = *(const float4*)(g_part + (size_t)row * HEAD + h4 * 4);
    const float4 o1 = *(const float4*)(g_part + ((size_t)ROWS_TOTAL + row) * HEAD + h4 * 4);
    float4 r;
    r.x = (o0.x * a0 + o1.x * a1) * inv;
    r.y = (o0.y * a0 + o1.y * a1) * inv;
    r.z = (o0.z * a0 + o1.z * a1) * inv;
    r.w = (o0.w * a0 + o1.w * a1) * inv;
    *(float4*)(out + (size_t)row * HEAD + h4 * 4) = r;
}

// ============================================================================
extern "C" void kernel_launch(void* const* d_in, const int* in_sizes, int n_in,
                              void* d_out, int out_size)
{
    const float* x  = (const float*)d_in[0];
    const float* Wq = (const float*)d_in[1];
    const float* Wk = (const float*)d_in[2];
    const float* Wv = (const float*)d_in[3];
    float* out = (float*)d_out;

    (void)cudaFuncSetAttribute(qkv_mma_kernel,
        cudaFuncAttributeMaxDynamicSharedMemorySize, QKV_SMEM);
    dim3 qgrid(ROWS_TOTAL / BM, 3);
    qkv_mma_kernel<<<qgrid, 256, QKV_SMEM>>>(x, Wq, Wk, Wv);

    (void)cudaFuncSetAttribute(attn_kernel,
        cudaFuncAttributeMaxDynamicSharedMemorySize, ATT_SMEM);
    attn_kernel<<<256, 256, ATT_SMEM>>>();

    combine_kernel<<<(ROWS_TOTAL * 32) / 256, 256>>>(out);
}

// round 13
// speedup vs baseline: 3.6867x; 1.0076x over previous
#include <cuda_runtime.h>
#include <cstdint>

#define EMBED 1024
#define HEAD  128
#define SEQ   4096
#define BATCH 4
#define ROWS_TOTAL (BATCH*SEQ)

typedef unsigned long long u64;
typedef unsigned int u32;

// scratch (device globals; no allocations allowed)
static __device__ float g_q [(size_t)ROWS_TOTAL * HEAD];    // fp32, [b][s][h'] h-interleaved
static __device__ float g_k [(size_t)ROWS_TOTAL * HEAD];    // tf32 BITS, [b][s][h'] h-interleaved
static __device__ float g_vT[(size_t)BATCH * HEAD * SEQ];   // tf32 BITS, [b][h][s'] s-interleaved
static __device__ float g_part[(size_t)2 * ROWS_TOTAL * HEAD];
static __device__ float g_mp[2 * ROWS_TOTAL];
static __device__ float g_lp[2 * ROWS_TOTAL];

__device__ __forceinline__ u64 pack2(float lo, float hi) {
    u64 r; asm("mov.b64 %0, {%1, %2};" : "=l"(r) : "f"(lo), "f"(hi)); return r;
}
__device__ __forceinline__ void unpk(u64 v, u32& lo, u32& hi) {
    asm("mov.b64 {%0, %1}, %2;" : "=r"(lo), "=r"(hi) : "l"(v));
}
__device__ __forceinline__ u32 tf32_rna(float f) {
    u32 r; asm("cvt.rna.tf32.f32 %0, %1;" : "=r"(r) : "f"(f)); return r;
}
// contracted-dim interleave within groups of 8: logical j -> physical
__device__ __forceinline__ int p8(int j) { return (j < 4) ? (j << 1) : (((j - 4) << 1) | 1); }
__device__ __forceinline__ u32 smem_u32(const void* p) {
    u32 a; asm("{ .reg .u64 t; cvta.to.shared.u64 t, %1; cvt.u32.u64 %0, t; }" : "=r"(a) : "l"(p));
    return a;
}
#define CP16(dst_u32, src_ptr) \
    asm volatile("cp.async.cg.shared.global [%0], [%1], 16;" :: "r"(dst_u32), "l"(src_ptr))
#define CP_COMMIT() asm volatile("cp.async.commit_group;" ::: "memory")
#define CP_WAIT0()  asm volatile("cp.async.wait_group 0;" ::: "memory")

__device__ __forceinline__ void mma_tf32(float* d, u32 a0, u32 a1, u32 a2, u32 a3,
                                         u32 b0, u32 b1) {
    asm volatile("mma.sync.aligned.m16n8k8.row.col.f32.tf32.tf32.f32 "
        "{%0,%1,%2,%3}, {%4,%5,%6,%7}, {%8,%9}, {%0,%1,%2,%3};"
        : "+f"(d[0]), "+f"(d[1]), "+f"(d[2]), "+f"(d[3])
        : "r"(a0), "r"(a1), "r"(a2), "r"(a3), "r"(b0), "r"(b1));
}

// ============================================================================
// Kernel 1: QKV via mma.sync tf32 (proven mainloop, untouched).
// Epilogue: Q fp32 h-interleaved; K,V stored as tf32_rna BITS (K h-interleaved
// natural rows; V transposed s-interleaved) so attention can cp.async them raw.
// ============================================================================
#define BM 128
#define BK 32
#define NCH (EMBED / BK)
#define AS_STR 36
#define BS_STR 136
#define AS_SZ (BM * AS_STR)
#define BS_SZ (BK * BS_STR)
#define QKV_SMEM ((AS_SZ + BS_SZ) * 2 * 4)

__global__ __launch_bounds__(256, 1) void qkv_mma_kernel(
    const float* __restrict__ x, const float* __restrict__ Wq,
    const float* __restrict__ Wk, const float* __restrict__ Wv)
{
    extern __shared__ __align__(16) float smq[];
    const int tid  = threadIdx.x;
    const int lane = tid & 31;
    const int wid  = tid >> 5;
    const int warp_m = (wid >> 2) * 64;
    const int warp_n = (wid & 3) * 32;
    const int m0 = blockIdx.x * BM;
    const int w  = blockIdx.y;
    const float* W = (w == 0) ? Wq : (w == 1) ? Wk : Wv;

    float* Asb[2] = { smq,         smq + AS_SZ + BS_SZ };
    float* Bsb[2] = { smq + AS_SZ, smq + 2 * AS_SZ + BS_SZ };

    float4 areg[4], breg[4];

#define LDG_CHUNK(c) do { \
    _Pragma("unroll") \
    for (int i = 0; i < 4; i++) { \
        int idx = tid + i * 256; \
        int row = idx >> 3, kq = idx & 7; \
        areg[i] = *(const float4*)(x + (size_t)(m0 + row) * EMBED + (c) * BK + kq * 4); \
        int k = idx >> 5, nq = idx & 31; \
        breg[i] = *(const float4*)(W + (size_t)((c) * BK + k) * HEAD + nq * 4); \
    } \
} while (0)

#define STS_CHUNK(buf) do { \
    _Pragma("unroll") \
    for (int i = 0; i < 4; i++) { \
        int idx = tid + i * 256; \
        int row = idx >> 3, kq = idx & 7; \
        uint4 av = { tf32_rna(areg[i].x), tf32_rna(areg[i].y), \
                     tf32_rna(areg[i].z), tf32_rna(areg[i].w) }; \
        *(uint4*)(Asb[buf] + row * AS_STR + kq * 4) = av; \
        int k = idx >> 5, nq = idx & 31; \
        uint4 bv = { tf32_rna(breg[i].x), tf32_rna(breg[i].y), \
                     tf32_rna(breg[i].z), tf32_rna(breg[i].w) }; \
        *(uint4*)(Bsb[buf] + k * BS_STR + nq * 4) = bv; \
    } \
} while (0)

    float acc[4][4][4];
#pragma unroll
    for (int mf = 0; mf < 4; mf++)
#pragma unroll
        for (int nf = 0; nf < 4; nf++)
#pragma unroll
            for (int i = 0; i < 4; i++) acc[mf][nf][i] = 0.0f;

    LDG_CHUNK(0);
    STS_CHUNK(0);
    __syncthreads();

    for (int c = 0; c < NCH; c++) {
        const int buf = c & 1;
        if (c + 1 < NCH) LDG_CHUNK(c + 1);

        const u32* ap = (const u32*)Asb[buf] + (warp_m + (lane >> 2)) * AS_STR + (lane & 3);
        const u32* bp = (const u32*)Bsb[buf] + (lane & 3) * BS_STR + warp_n + (lane >> 2);
#pragma unroll
        for (int ks = 0; ks < 4; ks++) {
            u32 a[4][4], b[4][2];
#pragma unroll
            for (int mf = 0; mf < 4; mf++) {
                const int o = mf * (16 * AS_STR) + ks * 8;
                a[mf][0] = ap[o];
                a[mf][1] = ap[o + 8 * AS_STR];
                a[mf][2] = ap[o + 4];
                a[mf][3] = ap[o + 8 * AS_STR + 4];
            }
#pragma unroll
            for (int nf = 0; nf < 4; nf++) {
                const int o = ks * (8 * BS_STR) + nf * 8;
                b[nf][0] = bp[o];
                b[nf][1] = bp[o + 4 * BS_STR];
            }
#pragma unroll
            for (int mf = 0; mf < 4; mf++)
#pragma unroll
                for (int nf = 0; nf < 4; nf++)
                    mma_tf32(acc[mf][nf], a[mf][0], a[mf][1], a[mf][2], a[mf][3],
                             b[nf][0], b[nf][1]);
        }

        if (c + 1 < NCH) {
            STS_CHUNK((c + 1) & 1);
            __syncthreads();
        }
    }

    const int lr = lane & 3;
    const int g0 = p8(2 * lr), g1 = p8(2 * lr + 1);
#pragma unroll
    for (int mf = 0; mf < 4; mf++) {
        const int mrow = m0 + warp_m + mf * 16 + (lane >> 2);
#pragma unroll
        for (int nf = 0; nf < 4; nf++) {
            const int nbase = warp_n + nf * 8;
            if (w == 2) {   // V -> g_vT[b][h][s'] as tf32 bits
                const int b0 = mrow >> 12, rb = mrow & (SEQ - 1);
                const int rbp = (rb & ~7) | p8(rb & 7);
                u32* vp = (u32*)(g_vT + ((size_t)b0 * HEAD + nbase + 2 * lr) * SEQ + rbp);
                vp[0]       = tf32_rna(acc[mf][nf][0]);
                vp[SEQ]     = tf32_rna(acc[mf][nf][1]);
                vp[8]       = tf32_rna(acc[mf][nf][2]);
                vp[SEQ + 8] = tf32_rna(acc[mf][nf][3]);
            } else if (w == 1) {  // K -> g_k as tf32 bits, h-interleaved
                u32* p0 = (u32*)(g_k + (size_t)mrow * HEAD + nbase);
                p0[g0]            = tf32_rna(acc[mf][nf][0]);
                p0[g1]            = tf32_rna(acc[mf][nf][1]);
                p0[g0 + 8 * HEAD] = tf32_rna(acc[mf][nf][2]);
                p0[g1 + 8 * HEAD] = tf32_rna(acc[mf][nf][3]);
            } else {              // Q fp32, h-interleaved
                float* p0 = g_q + (size_t)mrow * HEAD + nbase;
                p0[g0]            = acc[mf][nf][0];
                p0[g1]            = acc[mf][nf][1];
                p0[g0 + 8 * HEAD] = acc[mf][nf][2];
                p0[g1 + 8 * HEAD] = acc[mf][nf][3];
            }
        }
    }
#undef LDG_CHUNK
#undef STS_CHUNK
}

// ============================================================================
// Kernel 2: flash attention. Q-frags hoisted to registers; K/V tiles
// double-buffered via cp.async (prefetch kt+1 during kt compute).
// Smem: [K0][V0][K1][V1][Ps]; Q staged transiently in the K1/V1 region.
// ============================================================================
#define NEG_BIG (-3.0e38f)
#define M_INIT  (-1.0e30f)
#define QT_STR 136
#define KS_STR 136
#define VS_STR 72
#define PS_STR 72
#define KS_SZ (64 * KS_STR)
#define VS_SZ (128 * VS_STR)
#define PS_SZ (128 * PS_STR)
#define ATT_SMEM ((2 * (KS_SZ + VS_SZ) + PS_SZ) * 4)   // 180224 B

__global__ __launch_bounds__(256, 1) void attn_kernel()
{
    extern __shared__ __align__(16) float smf[];
    float* Ks0 = smf;
    float* Vs0 = Ks0 + KS_SZ;
    float* Ks1 = Vs0 + VS_SZ;
    float* Vs1 = Ks1 + KS_SZ;
    float* Ps  = Vs1 + VS_SZ;
    float* Qtmp = Ks1;               // transient Q staging (128*136 <= KS_SZ+VS_SZ)

    const int tid  = threadIdx.x;
    const int lane = tid & 31;
    const int w    = tid >> 5;
    const int id = blockIdx.x;
    const int qt = 31 - (id >> 3);
    const int z  = id & 1;
    const int b  = (id >> 1) & 3;
    const int q0 = qt * 128;
    const float scale = 0.08838834764831845f;

    const int lq = lane >> 2;
    const int lr = lane & 3;
    const int rlo = w * 16 + lq, rhi = rlo + 8;
    const int g0 = p8(2 * lr), g1 = p8(2 * lr + 1);

    // ---- stage Q (scaled + rna) into transient smem, extract frags to regs ----
    {
        const float* qg = g_q + ((size_t)b * SEQ + q0) * HEAD;
#pragma unroll
        for (int i = 0; i < 16; i++) {
            int idx = tid + i * 256;
            int h4 = idx >> 7, r = idx & 127;
            float4 v = *(const float4*)(qg + (size_t)r * HEAD + h4 * 4);
            uint4 t = { tf32_rna(v.x * scale), tf32_rna(v.y * scale),
                        tf32_rna(v.z * scale), tf32_rna(v.w * scale) };
            *(uint4*)(Qtmp + r * QT_STR + h4 * 4) = t;
        }
    }
    __syncthreads();
    u32 qa[16][4];
    {
        const u32* apl = (const u32*)Qtmp + rlo * QT_STR + 2 * lr;
        const u32* aph = (const u32*)Qtmp + rhi * QT_STR + 2 * lr;
#pragma unroll
        for (int ks = 0; ks < 16; ks++) {
            unpk(*(const u64*)(apl + ks * 8), qa[ks][0], qa[ks][2]);
            unpk(*(const u64*)(aph + ks * 8), qa[ks][1], qa[ks][3]);
        }
    }
    __syncthreads();

#define LOAD_TILE(ktv, Kd, Vd) do { \
    const float* kg = g_k + ((size_t)b * SEQ + (size_t)(ktv) * 64) * HEAD; \
    const float* vg = g_vT + (size_t)b * HEAD * SEQ + (size_t)(ktv) * 64; \
    _Pragma("unroll") \
    for (int i = 0; i < 8; i++) { \
        int idx = tid + i * 256; \
        int e4 = idx & 31, r = idx >> 5; \
        CP16(smem_u32((Kd) + r * KS_STR + e4 * 4), kg + (size_t)r * HEAD + e4 * 4); \
        int h = idx >> 4, k4 = idx & 15; \
        CP16(smem_u32((Vd) + h * VS_STR + k4 * 4), vg + (size_t)h * SEQ + k4 * 4); \
    } \
} while (0)

    float O[16][4];
#pragma unroll
    for (int nf = 0; nf < 16; nf++)
#pragma unroll
        for (int i = 0; i < 4; i++) O[nf][i] = 0.0f;
    float mlo = M_INIT, mhi = M_INIT, llo = 0.0f, lhi = 0.0f;

    const int kt0 = z ? (qt + 1) : 0;
    const int kt1 = z ? (2 * qt + 2) : (qt + 1);

    // preload first tile
    LOAD_TILE(kt0, Ks0, Vs0);
    CP_COMMIT();
    CP_WAIT0();
    __syncthreads();

    for (int kt = kt0; kt < kt1; kt++) {
        const int st = (kt - kt0) & 1;
        float* Kc = st ? Ks1 : Ks0;
        float* Vc = st ? Vs1 : Vs0;

        if (kt + 1 < kt1) {
            LOAD_TILE(kt + 1, st ? Ks0 : Ks1, st ? Vs0 : Vs1);
            CP_COMMIT();
        }

        // ---- scores: warp m16 x n64, Q in regs, B via LDS.64 ----
        float acc[8][4];
#pragma unroll
        for (int nf = 0; nf < 8; nf++)
#pragma unroll
            for (int i = 0; i < 4; i++) acc[nf][i] = 0.0f;

        const u32* bp = (const u32*)Kc + lq * KS_STR + 2 * lr;
#pragma unroll 2
        for (int ks = 0; ks < 16; ks++) {
            const int ko = ks * 8;
#pragma unroll
            for (int nf = 0; nf < 8; nf++) {
                u32 b0, b1;
                unpk(*(const u64*)(bp + nf * (8 * KS_STR) + ko), b0, b1);
                mma_tf32(acc[nf], qa[ks][0], qa[ks][1], qa[ks][2], qa[ks][3], b0, b1);
            }
        }

        if (kt >= 2 * qt) {
            const int koff = (kt - 2 * qt) * 64;
#pragma unroll
            for (int nf = 0; nf < 8; nf++) {
                const int c0 = koff + nf * 8 + 2 * lr;
                if (c0 > rlo)     acc[nf][0] = NEG_BIG;
                if (c0 + 1 > rlo) acc[nf][1] = NEG_BIG;
                if (c0 > rhi)     acc[nf][2] = NEG_BIG;
                if (c0 + 1 > rhi) acc[nf][3] = NEG_BIG;
            }
        }

        // ---- online softmax (quad reduction) ----
        float rmlo = NEG_BIG, rmhi = NEG_BIG;
#pragma unroll
        for (int nf = 0; nf < 8; nf++) {
            rmlo = fmaxf(rmlo, fmaxf(acc[nf][0], acc[nf][1]));
            rmhi = fmaxf(rmhi, fmaxf(acc[nf][2], acc[nf][3]));
        }
#pragma unroll
        for (int off = 1; off < 4; off <<= 1) {
            rmlo = fmaxf(rmlo, __shfl_xor_sync(0xffffffffu, rmlo, off));
            rmhi = fmaxf(rmhi, __shfl_xor_sync(0xffffffffu, rmhi, off));
        }
        const float nmlo = fmaxf(mlo, rmlo), nmhi = fmaxf(mhi, rmhi);
        const float alo = __expf(mlo - nmlo), ahi = __expf(mhi - nmhi);
        float slo = 0.0f, shi = 0.0f;
        u32* PsU = (u32*)Ps;
#pragma unroll
        for (int nf = 0; nf < 8; nf++) {
            float p0 = __expf(acc[nf][0] - nmlo);
            float p1 = __expf(acc[nf][1] - nmlo);
            float p2 = __expf(acc[nf][2] - nmhi);
            float p3 = __expf(acc[nf][3] - nmhi);
            slo += p0 + p1; shi += p2 + p3;
            PsU[rlo * PS_STR + nf * 8 + g0] = tf32_rna(p0);
            PsU[rlo * PS_STR + nf * 8 + g1] = tf32_rna(p1);
            PsU[rhi * PS_STR + nf * 8 + g0] = tf32_rna(p2);
            PsU[rhi * PS_STR + nf * 8 + g1] = tf32_rna(p3);
        }
#pragma unroll
        for (int off = 1; off < 4; off <<= 1) {
            slo += __shfl_xor_sync(0xffffffffu, slo, off);
            shi += __shfl_xor_sync(0xffffffffu, shi, off);
        }
        llo = llo * alo + slo; mlo = nmlo;
        lhi = lhi * ahi + shi; mhi = nmhi;
        __syncwarp();

        // ---- O rescale + AV: warp m16 x n128, LDS.64 frags ----
#pragma unroll
        for (int nf = 0; nf < 16; nf++) {
            O[nf][0] *= alo; O[nf][1] *= alo;
            O[nf][2] *= ahi; O[nf][3] *= ahi;
        }
        const u32* pal = (const u32*)Ps + rlo * PS_STR + 2 * lr;
        const u32* pah = (const u32*)Ps + rhi * PS_STR + 2 * lr;
        const u32* vb  = (const u32*)Vc + lq * VS_STR + 2 * lr;
#pragma unroll 2
        for (int ks = 0; ks < 8; ks++) {
            const int ko = ks * 8;
            u32 a0, a1, a2, a3;
            unpk(*(const u64*)(pal + ko), a0, a2);
            unpk(*(const u64*)(pah + ko), a1, a3);
#pragma unroll
            for (int nf = 0; nf < 16; nf++) {
                u32 b0, b1;
                unpk(*(const u64*)(vb + nf * (8 * VS_STR) + ko), b0, b1);
                mma_tf32(O[nf], a0, a1, a2, a3, b0, b1);
            }
        }

        if (kt + 1 < kt1) CP_WAIT0();   // prefetched tile arrived
        __syncthreads();                 // all warps done with current stage
    }
#undef LOAD_TILE

    // ---- write partials (C-frag layout; h natural) ----
    const size_t base = (size_t)(z * BATCH + b) * SEQ + q0;
    float* oplo = g_part + (base + rlo) * HEAD + 2 * lr;
    float* ophi = g_part + (base + rhi) * HEAD + 2 * lr;
#pragma unroll
    for (int nf = 0; nf < 16; nf++) {
        *(u64*)(oplo + nf * 8) = pack2(O[nf][0], O[nf][1]);
        *(u64*)(ophi + nf * 8) = pack2(O[nf][2], O[nf][3]);
    }
    if (lr == 0) {
        g_mp[base + rlo] = mlo; g_lp[base + rlo] = llo;
        g_mp[base + rhi] = mhi; g_lp[base + rhi] = lhi;
    }
}

// ============================================================================
// Kernel 3: merge split-K partials
// ============================================================================
__global__ __launch_bounds__(256) void combine_kernel(float* __restrict__ out)
{
    const int idx = blockIdx.x * 256 + threadIdx.x;
    const int row = idx >> 5, h4 = idx & 31;
    const float m0 = g_mp[row], m1 = g_mp[ROWS_TOTAL + row];
    const float l0 = g_lp[row], l1 = g_lp[ROWS_TOTAL + row];
    const float mm = fmaxf(m0, m1);
    const float a0 = __expf(m0 - mm), a1 = __expf(m1 - mm);
    const float inv = 1.0f / (l0 * a0 + l1 * a1);
    const float4 o0 = *(const float4*)(g_part + (size_t)row * HEAD + h4 * 4);
    const float4 o1 = *(const float4*)(g_part + ((size_t)ROWS_TOTAL + row) * HEAD + h4 * 4);
    float4 r;
    r.x = (o0.x * a0 + o1.x * a1) * inv;
    r.y = (o0.y * a0 + o1.y * a1) * inv;
    r.z = (o0.z * a0 + o1.z * a1) * inv;
    r.w = (o0.w * a0 + o1.w * a1) * inv;
    *(float4*)(out + (size_t)row * HEAD + h4 * 4) = r;
}

// ============================================================================
extern "C" void kernel_launch(void* const* d_in, const int* in_sizes, int n_in,
                              void* d_out, int out_size)
{
    const float* x  = (const float*)d_in[0];
    const float* Wq = (const float*)d_in[1];
    const float* Wk = (const float*)d_in[2];
    const float* Wv = (const float*)d_in[3];
    float* out = (float*)d_out;

    (void)cudaFuncSetAttribute(qkv_mma_kernel,
        cudaFuncAttributeMaxDynamicSharedMemorySize, QKV_SMEM);
    dim3 qgrid(ROWS_TOTAL / BM, 3);
    qkv_mma_kernel<<<qgrid, 256, QKV_SMEM>>>(x, Wq, Wk, Wv);

    (void)cudaFuncSetAttribute(attn_kernel,
        cudaFuncAttributeMaxDynamicSharedMemorySize, ATT_SMEM);
    attn_kernel<<<256, 256, ATT_SMEM>>>();

    combine_kernel<<<(ROWS_TOTAL * 32) / 256, 256>>>(out);
}